// round 3
// baseline (speedup 1.0000x reference)
#include <cuda_runtime.h>
#include <math.h>

#define Bn    8
#define NPIX  (512*512)
#define NBINS 256
#define NB    128
#define NT    1024
#define NUNITS (NB*4)

#define OFF0 0u
#define OFF1 2097152u
#define OFF2 2621440u
#define OFF3 2752512u
#define OFF4 2785280u

#define G0 0.12007823f
#define G1 0.23388087f
#define G2 0.29208180f
__device__ __constant__ float c_g[5] = {G0, G1, G2, G1, G0};

__device__ float d_Lp[2793472];
__device__ float d_Lt[2793472];
__device__ int   d_histp[Bn*3*NBINS];
__device__ int   d_histt[Bn*3*NBINS];
__device__ float d_l1sum;
__device__ float d_ssim_sum[Bn*5];
__device__ float d_cs_sum[Bn*5];
__device__ unsigned g_cnt, g_done, g_flag;

// ---------------- grid barrier ---------------------------------------------
__device__ __forceinline__ unsigned ld_flag()
{
    unsigned v;
    asm volatile("ld.global.cg.u32 %0, [%1];" : "=r"(v) : "l"(&g_flag) : "memory");
    return v;
}

__device__ __forceinline__ void gsync(unsigned k)
{
    __syncthreads();
    if (threadIdx.x == 0) {
        __threadfence();
        unsigned r = atomicAdd(&g_cnt, 1u);
        if (r == k*NB - 1u) {
            atomicExch(&g_flag, k);          // release
        } else {
            while (ld_flag() < k) __nanosleep(128);
        }
    }
    __syncthreads();
}

// ---------------- shared memory layout --------------------------------------
struct Unit {
    float t1[12][36];
    float t2[12][36];
    float m[5][12][32];
    float redS[8], redC[8];
};

union SMem {
    Unit u[4];
    struct { int hist[6*NBINS]; float red[32]; } lab;
};

// ---------------- RGB -> normalized LAB -------------------------------------
__device__ __forceinline__ float srgb_lin(float x)
{
    if (x <= 0.04045f) return x * (1.f/12.92f);
    float y = (fmaxf(x, 1e-4f) + 0.055f) * (1.f/1.055f);
    return __powf(y, 2.4f);
}

__device__ __forceinline__ float f_lab(float t)
{
    const float e3 = 0.008856451679035631f;
    if (t <= e3) return t * (841.f/108.f) + (4.f/29.f);
    return __powf(fmaxf(t, 1e-4f), 1.f/3.f);
}

__device__ __forceinline__ void rgb2lab_norm(float r, float g, float b,
                                             float& L, float& A, float& Bc)
{
    float lr = srgb_lin(r), lg = srgb_lin(g), lb = srgb_lin(b);
    float X = lr*0.412453f + lg*0.357580f + lb*0.180423f;
    float Y = lr*0.212671f + lg*0.715160f + lb*0.072169f;
    float Z = lr*0.019334f + lg*0.119193f + lb*0.950227f;
    X *= (1.f/0.950456f);
    Z *= (1.f/1.088754f);
    float fx = f_lab(X), fy = f_lab(Y), fz = f_lab(Z);
    float Ll = 116.f*fy - 16.f;
    float Aa = 500.f*(fx - fy);
    float Bb = 200.f*(fy - fz);
    L  = fminf(fmaxf(Ll * 0.01f,                 0.f), 1.f);
    A  = fminf(fmaxf((Aa*(1.f/110.f)+1.f)*0.5f,  0.f), 1.f);
    Bc = fminf(fmaxf((Bb*(1.f/110.f)+1.f)*0.5f,  0.f), 1.f);
}

__device__ __forceinline__ int bin_of(float v)
{
    int b = (int)(v * 256.f);
    return b > 255 ? 255 : b;
}

// ---------------- SSIM tile (one 32x8 output tile per 256-thread unit) -----
// NOTE: uses block-wide __syncthreads; all 4 units in a block always execute
// the same number of tile calls per phase, so syncs stay aligned.
__device__ __forceinline__ void ssim_tile(Unit& U, int ut,
                                          unsigned off, unsigned offo,
                                          int Hl, int lvl, int b,
                                          int tix, int tiy, bool pool)
{
    const float* i1 = d_Lp + off + (size_t)b*Hl*Hl;
    const float* i2 = d_Lt + off + (size_t)b*Hl*Hl;
    int ox = tix*32, oy = tiy*8;

    for (int i = ut; i < 12*36; i += 256) {
        int r = i/36, c = i%36;
        int gy = oy + r - 2, gx = ox + c - 2;
        float v1 = 0.f, v2 = 0.f;
        if (gy >= 0 && gy < Hl && gx >= 0 && gx < Hl) {
            v1 = i1[gy*Hl + gx];
            v2 = i2[gy*Hl + gx];
        }
        U.t1[r][c] = v1;
        U.t2[r][c] = v2;
    }
    __syncthreads();

    for (int i = ut; i < 12*32; i += 256) {
        int r = i >> 5, c = i & 31;
        float m1 = 0.f, m2 = 0.f, a11 = 0.f, a22 = 0.f, a12 = 0.f;
#pragma unroll
        for (int k = 0; k < 5; k++) {
            float g = c_g[k];
            float a = U.t1[r][c+k];
            float q = U.t2[r][c+k];
            float ga = g*a, gq = g*q;
            m1 += ga;  m2 += gq;
            a11 += ga*a; a22 += gq*q; a12 += ga*q;
        }
        U.m[0][r][c] = m1; U.m[1][r][c] = m2;
        U.m[2][r][c] = a11; U.m[3][r][c] = a22; U.m[4][r][c] = a12;
    }
    __syncthreads();

    int tx = ut & 31, ty = ut >> 5;
    float mu1 = 0.f, mu2 = 0.f, x11 = 0.f, x22 = 0.f, x12 = 0.f;
#pragma unroll
    for (int k = 0; k < 5; k++) {
        float g = c_g[k];
        mu1 += g*U.m[0][ty+k][tx];
        mu2 += g*U.m[1][ty+k][tx];
        x11 += g*U.m[2][ty+k][tx];
        x22 += g*U.m[3][ty+k][tx];
        x12 += g*U.m[4][ty+k][tx];
    }

    float s1  = x11 - mu1*mu1;
    float s2  = x22 - mu2*mu2;
    float s12 = x12 - mu1*mu2;
    const float C1 = 1e-4f, C2 = 9e-4f;
    float den  = s1 + s2 + C2;
    float num2 = 2.f*s12 + C2;
    float cs   = num2 / den;
    float ssim = ((2.f*mu1*mu2 + C1) * num2) / ((mu1*mu1 + mu2*mu2 + C1) * den);

    if (pool && ut < 64) {
        int rp = ut >> 4, cp = ut & 15;
        int Ho = Hl >> 1;
        float p1 = 0.25f*(U.t1[2*rp+2][2*cp+2] + U.t1[2*rp+2][2*cp+3] +
                          U.t1[2*rp+3][2*cp+2] + U.t1[2*rp+3][2*cp+3]);
        float p2 = 0.25f*(U.t2[2*rp+2][2*cp+2] + U.t2[2*rp+2][2*cp+3] +
                          U.t2[2*rp+3][2*cp+2] + U.t2[2*rp+3][2*cp+3]);
        size_t o = (size_t)offo + (size_t)b*Ho*Ho + (size_t)((oy>>1)+rp)*Ho + (ox>>1)+cp;
        d_Lp[o] = p1;
        d_Lt[o] = p2;
    }

    float vs = ssim, vc = cs;
    for (int o = 16; o; o >>= 1) {
        vs += __shfl_down_sync(0xffffffffu, vs, o);
        vc += __shfl_down_sync(0xffffffffu, vc, o);
    }
    int lane = ut & 31, wid = ut >> 5;
    if (lane == 0) { U.redS[wid] = vs; U.redC[wid] = vc; }
    __syncthreads();
    if (wid == 0) {
        vs = (lane < 8) ? U.redS[lane] : 0.f;
        vc = (lane < 8) ? U.redC[lane] : 0.f;
        for (int o = 4; o; o >>= 1) {
            vs += __shfl_down_sync(0xffffffffu, vs, o);
            vc += __shfl_down_sync(0xffffffffu, vc, o);
        }
        if (lane == 0) {
            atomicAdd(&d_ssim_sum[b*5 + lvl], vs);
            atomicAdd(&d_cs_sum[b*5 + lvl], vc);
        }
    }
    __syncthreads();
}

__device__ __forceinline__ void ssim_level(Unit& U, int ut, int unit,
                                           unsigned off, unsigned offo,
                                           int Hl, int lvl, bool pool, int iters)
{
    int tpx = Hl >> 5, tpy = Hl >> 3, tpi = tpx*tpy;
    for (int i = 0; i < iters; i++) {
        int t = unit + i*NUNITS;
        int b = t / tpi, r = t % tpi;
        ssim_tile(U, ut, off, offo, Hl, lvl, b, r % tpx, r / tpx, pool);
    }
}

// ---------------- the one kernel --------------------------------------------
__global__ void __launch_bounds__(NT, 1)
k_all(const float* __restrict__ pred, const float* __restrict__ tgt,
      float* __restrict__ out)
{
    __shared__ SMem sm;
    __shared__ float l1img[8], msarr[8];

    int tid  = threadIdx.x;
    int ublk = tid >> 8;
    int ut   = tid & 255;
    int unit = blockIdx.x*4 + ublk;
    Unit& U  = sm.u[ublk];

    // ================= phase 1: LAB + histogram + L1 =======================
    {
        for (int i = tid; i < 6*NBINS; i += NT) sm.lab.hist[i] = 0;
        __syncthreads();

        int img   = blockIdx.x >> 4;      // 16 blocks per image
        int chunk = blockIdx.x & 15;
        size_t ibase = (size_t)img*3*NPIX;
        float l1acc = 0.f;

#pragma unroll
        for (int it = 0; it < 4; it++) {
            int p = chunk*16384 + (it*NT + tid)*4;
            float4 pr = *(const float4*)(pred + ibase + p);
            float4 pg = *(const float4*)(pred + ibase + NPIX + p);
            float4 pb = *(const float4*)(pred + ibase + 2*NPIX + p);
            float4 tr = *(const float4*)(tgt  + ibase + p);
            float4 tg = *(const float4*)(tgt  + ibase + NPIX + p);
            float4 tb = *(const float4*)(tgt  + ibase + 2*NPIX + p);

            float4 plo, tlo;
            float* prf = &pr.x; float* pgf = &pg.x; float* pbf = &pb.x;
            float* trf = &tr.x; float* tgf = &tg.x; float* tbf = &tb.x;
            float* plf = &plo.x; float* tlf = &tlo.x;
#pragma unroll
            for (int j = 0; j < 4; j++) {
                float pl, pa, pbc, tl, ta, tbc;
                rgb2lab_norm(prf[j], pgf[j], pbf[j], pl, pa, pbc);
                rgb2lab_norm(trf[j], tgf[j], tbf[j], tl, ta, tbc);
                plf[j] = pl; tlf[j] = tl;
                atomicAdd(&sm.lab.hist[0*NBINS + bin_of(pl)],  1);
                atomicAdd(&sm.lab.hist[1*NBINS + bin_of(pa)],  1);
                atomicAdd(&sm.lab.hist[2*NBINS + bin_of(pbc)], 1);
                atomicAdd(&sm.lab.hist[3*NBINS + bin_of(tl)],  1);
                atomicAdd(&sm.lab.hist[4*NBINS + bin_of(ta)],  1);
                atomicAdd(&sm.lab.hist[5*NBINS + bin_of(tbc)], 1);
                l1acc += fabsf(pl-tl) + fabsf(pa-ta) + fabsf(pbc-tbc);
            }
            *(float4*)(d_Lp + (size_t)img*NPIX + p) = plo;
            *(float4*)(d_Lt + (size_t)img*NPIX + p) = tlo;
        }
        __syncthreads();

        for (int i = tid; i < 3*NBINS; i += NT) {
            int hp = sm.lab.hist[i], ht = sm.lab.hist[3*NBINS + i];
            if (hp) atomicAdd(&d_histp[img*3*NBINS + i], hp);
            if (ht) atomicAdd(&d_histt[img*3*NBINS + i], ht);
        }

        float v = l1acc;
        for (int o = 16; o; o >>= 1) v += __shfl_down_sync(0xffffffffu, v, o);
        int lane = tid & 31, wid = tid >> 5;
        if (lane == 0) sm.lab.red[wid] = v;
        __syncthreads();
        if (wid == 0) {
            v = sm.lab.red[lane];
            for (int o = 16; o; o >>= 1) v += __shfl_down_sync(0xffffffffu, v, o);
            if (lane == 0) atomicAdd(&d_l1sum, v);
        }
        __syncthreads();  // protect sm.lab before union reuse
    }

    gsync(1);

    // ================= SSIM pyramid =========================================
    ssim_level(U, ut, unit, OFF0, OFF1, 512, 0, true, 16);
    gsync(2);
    ssim_level(U, ut, unit, OFF1, OFF2, 256, 1, true, 4);
    gsync(3);
    ssim_level(U, ut, unit, OFF2, OFF3, 128, 2, true, 1);
    gsync(4);

    // L3 + L4: one block per image, block-local sync only
    if (blockIdx.x < 8) {
        int b = blockIdx.x;
#pragma unroll
        for (int i = 0; i < 4; i++) {
            int t = ublk + i*4;                    // 16 tiles (2x8)
            ssim_tile(U, ut, OFF3, OFF4, 64, 3, b, t % 2, t / 2, true);
        }
        __syncthreads();
        {
            int t = ublk;                          // 4 tiles (1x4)
            ssim_tile(U, ut, OFF4, 0, 32, 4, b, 0, t, false);
        }
    }

    gsync(5);

    // ================= final scalar assembly (block 0) ======================
    if (blockIdx.x == 0) {
        int t = tid;
        if (t < 256) {
            int b = t >> 5, lane = t & 31;
            float s = 0.f;
            for (int i = lane; i < 3*NBINS; i += 32) {
                int d = d_histp[b*3*NBINS + i] - d_histt[b*3*NBINS + i];
                s += fabsf((float)d);
            }
            for (int o = 16; o; o >>= 1) s += __shfl_down_sync(0xffffffffu, s, o);
            if (lane == 0) l1img[b] = s * (1.f/768.f);
        }
        __syncthreads();

        if (t < 8) {
            const float wts[5] = {0.0448f, 0.2856f, 0.3001f, 0.2363f, 0.1333f};
            const float cnt[5] = {262144.f, 65536.f, 16384.f, 4096.f, 1024.f};
            float ms = 1.f;
            for (int l = 0; l < 4; l++) {
                float mcs = d_cs_sum[t*5 + l] / cnt[l];
                ms *= powf((mcs + 1.f)*0.5f, wts[l]);
            }
            float mss4 = d_ssim_sum[t*5 + 4] / cnt[4];
            ms *= powf((mss4 + 1.f)*0.5f, wts[4]);
            msarr[t] = 1.f - ms;
        }
        __syncthreads();

        if (t == 0) {
            float hist_loss = 0.f;
            for (int i = 0; i < 8; i++)
                hist_loss += exp2f((float)(i - 8)) * (l1img[i] + 1.f);
            float scaler = (float)NPIX / 20.f;
            hist_loss = hist_loss / 8.f / scaler;
            float lab_l1 = d_l1sum / (float)(Bn*3*NPIX);
            float sl = 0.f;
            for (int i = 0; i < 8; i++) sl += msarr[i];
            sl *= (1.f/8.f);
            out[0] = lab_l1 + hist_loss;
            out[1] = sl;
        }
        __syncthreads();

        // re-zero accumulators for next replay (only block 0 touches them now)
        for (int i = tid; i < 3*NBINS*Bn; i += NT) { d_histp[i] = 0; d_histt[i] = 0; }
        if (tid < Bn*5) { d_ssim_sum[tid] = 0.f; d_cs_sum[tid] = 0.f; }
        if (tid == 0) d_l1sum = 0.f;
    }

    // ================= exit: last block out resets barrier state ============
    __syncthreads();
    if (threadIdx.x == 0) {
        __threadfence();
        unsigned r = atomicAdd(&g_done, 1u);
        if (r == NB - 1u) {           // provably the last block; nobody spins anymore
            g_cnt  = 0u;
            g_done = 0u;
            g_flag = 0u;
            __threadfence();
        }
    }
}

// ---------------- launch ----------------------------------------------------
extern "C" void kernel_launch(void* const* d_in, const int* in_sizes, int n_in,
                              void* d_out, int out_size)
{
    const float* pred = (const float*)d_in[1];
    const float* tgt  = (const float*)d_in[2];
    float* out = (float*)d_out;

    k_all<<<NB, NT>>>(pred, tgt, out);
}

// round 4
// speedup vs baseline: 1.0074x; 1.0074x over previous
#include <cuda_runtime.h>
#include <math.h>

#define Bn    8
#define NPIX  (512*512)
#define NBINS 256

#define OFF0 0u
#define OFF1 2097152u
#define OFF2 2621440u
#define OFF3 2752512u
#define OFF4 2785280u

#define G0 0.12007823f
#define G1 0.23388087f
#define G2 0.29208180f
__device__ __constant__ float c_g[5] = {G0, G1, G2, G1, G0};

__device__ float d_Lp[2793472];
__device__ float d_Lt[2793472];
__device__ int   d_histp[Bn*3*NBINS];
__device__ int   d_histt[Bn*3*NBINS];
__device__ float d_l1sum;
__device__ float d_ssim_sum[Bn*5];
__device__ float d_cs_sum[Bn*5];
__device__ unsigned g_done;

// ---------------- RGB -> normalized LAB -------------------------------------
__device__ __forceinline__ float srgb_lin(float x)
{
    if (x <= 0.04045f) return x * (1.f/12.92f);
    float y = (fmaxf(x, 1e-4f) + 0.055f) * (1.f/1.055f);
    return __powf(y, 2.4f);
}

__device__ __forceinline__ float f_lab(float t)
{
    const float e3 = 0.008856451679035631f;
    if (t <= e3) return t * (841.f/108.f) + (4.f/29.f);
    return __powf(fmaxf(t, 1e-4f), 1.f/3.f);
}

__device__ __forceinline__ void rgb2lab_norm(float r, float g, float b,
                                             float& L, float& A, float& Bc)
{
    float lr = srgb_lin(r), lg = srgb_lin(g), lb = srgb_lin(b);
    float X = lr*0.412453f + lg*0.357580f + lb*0.180423f;
    float Y = lr*0.212671f + lg*0.715160f + lb*0.072169f;
    float Z = lr*0.019334f + lg*0.119193f + lb*0.950227f;
    X *= (1.f/0.950456f);
    Z *= (1.f/1.088754f);
    float fx = f_lab(X), fy = f_lab(Y), fz = f_lab(Z);
    float Ll = 116.f*fy - 16.f;
    float Aa = 500.f*(fx - fy);
    float Bb = 200.f*(fy - fz);
    L  = fminf(fmaxf(Ll * 0.01f,                 0.f), 1.f);
    A  = fminf(fmaxf((Aa*(1.f/110.f)+1.f)*0.5f,  0.f), 1.f);
    Bc = fminf(fmaxf((Bb*(1.f/110.f)+1.f)*0.5f,  0.f), 1.f);
}

__device__ __forceinline__ int bin_of(float v)
{
    int b = (int)(v * 256.f);
    return b > 255 ? 255 : b;
}

// ---------------- fused LAB + histogram + L1 + L-channel store -------------
// grid (128, 8) x 256 threads; 8 px/thread (2 float4 iters)
__global__ void k_lab(const float* __restrict__ pred, const float* __restrict__ tgt)
{
    __shared__ int   sh[6*NBINS];
    __shared__ float red[8];
    int b   = blockIdx.y;
    int tid = threadIdx.x;

    for (int i = tid; i < 6*NBINS; i += 256) sh[i] = 0;
    __syncthreads();

    const size_t ibase = (size_t)b*3*NPIX;
    float l1acc = 0.f;

#pragma unroll
    for (int it = 0; it < 2; it++) {
        int p = blockIdx.x*2048 + it*1024 + tid*4;
        float4 pr = *(const float4*)(pred + ibase + p);
        float4 pg = *(const float4*)(pred + ibase + NPIX + p);
        float4 pb = *(const float4*)(pred + ibase + 2*NPIX + p);
        float4 tr = *(const float4*)(tgt  + ibase + p);
        float4 tg = *(const float4*)(tgt  + ibase + NPIX + p);
        float4 tb = *(const float4*)(tgt  + ibase + 2*NPIX + p);

        float4 plo, tlo;
        float* prf = &pr.x; float* pgf = &pg.x; float* pbf = &pb.x;
        float* trf = &tr.x; float* tgf = &tg.x; float* tbf = &tb.x;
        float* plf = &plo.x; float* tlf = &tlo.x;
#pragma unroll
        for (int j = 0; j < 4; j++) {
            float pl, pa, pbc, tl, ta, tbc;
            rgb2lab_norm(prf[j], pgf[j], pbf[j], pl, pa, pbc);
            rgb2lab_norm(trf[j], tgf[j], tbf[j], tl, ta, tbc);
            plf[j] = pl; tlf[j] = tl;
            atomicAdd(&sh[0*NBINS + bin_of(pl)],  1);
            atomicAdd(&sh[1*NBINS + bin_of(pa)],  1);
            atomicAdd(&sh[2*NBINS + bin_of(pbc)], 1);
            atomicAdd(&sh[3*NBINS + bin_of(tl)],  1);
            atomicAdd(&sh[4*NBINS + bin_of(ta)],  1);
            atomicAdd(&sh[5*NBINS + bin_of(tbc)], 1);
            l1acc += fabsf(pl-tl) + fabsf(pa-ta) + fabsf(pbc-tbc);
        }
        *(float4*)(d_Lp + (size_t)b*NPIX + p) = plo;
        *(float4*)(d_Lt + (size_t)b*NPIX + p) = tlo;
    }
    __syncthreads();

    for (int i = tid; i < 3*NBINS; i += 256) {
        int hp = sh[i], ht = sh[3*NBINS + i];
        if (hp) atomicAdd(&d_histp[b*3*NBINS + i], hp);
        if (ht) atomicAdd(&d_histt[b*3*NBINS + i], ht);
    }

    float v = l1acc;
    for (int o = 16; o; o >>= 1) v += __shfl_down_sync(0xffffffffu, v, o);
    int lane = tid & 31, wid = tid >> 5;
    if (lane == 0) red[wid] = v;
    __syncthreads();
    if (wid == 0) {
        v = (lane < 8) ? red[lane] : 0.f;
        for (int o = 4; o; o >>= 1) v += __shfl_down_sync(0xffffffffu, v, o);
        if (lane == 0) atomicAdd(&d_l1sum, v);
    }
}

// ---------------- shared SSIM tile machinery --------------------------------
struct Unit {
    float t1[12][36];
    float t2[12][36];
    float m[5][12][32];
    float redS[8], redC[8];
};

// One 32x8 output tile per 256-thread unit. Returns per-thread ssim/cs.
// Contains block-wide __syncthreads: all units in the block must call in lockstep.
__device__ __forceinline__ void ssim_tile(Unit& U, int ut,
                                          unsigned off, unsigned offo,
                                          int Hl, int b, int tix, int tiy,
                                          bool pool, float& oS, float& oC)
{
    const float* i1 = d_Lp + off + (size_t)b*Hl*Hl;
    const float* i2 = d_Lt + off + (size_t)b*Hl*Hl;
    int ox = tix*32, oy = tiy*8;

    for (int i = ut; i < 12*36; i += 256) {
        int r = i/36, c = i%36;
        int gy = oy + r - 2, gx = ox + c - 2;
        float v1 = 0.f, v2 = 0.f;
        if (gy >= 0 && gy < Hl && gx >= 0 && gx < Hl) {
            v1 = i1[gy*Hl + gx];
            v2 = i2[gy*Hl + gx];
        }
        U.t1[r][c] = v1;
        U.t2[r][c] = v2;
    }
    __syncthreads();

    for (int i = ut; i < 12*32; i += 256) {
        int r = i >> 5, c = i & 31;
        float m1 = 0.f, m2 = 0.f, a11 = 0.f, a22 = 0.f, a12 = 0.f;
#pragma unroll
        for (int k = 0; k < 5; k++) {
            float g = c_g[k];
            float a = U.t1[r][c+k];
            float q = U.t2[r][c+k];
            float ga = g*a, gq = g*q;
            m1 += ga;  m2 += gq;
            a11 += ga*a; a22 += gq*q; a12 += ga*q;
        }
        U.m[0][r][c] = m1; U.m[1][r][c] = m2;
        U.m[2][r][c] = a11; U.m[3][r][c] = a22; U.m[4][r][c] = a12;
    }
    __syncthreads();

    int tx = ut & 31, ty = ut >> 5;
    float mu1 = 0.f, mu2 = 0.f, x11 = 0.f, x22 = 0.f, x12 = 0.f;
#pragma unroll
    for (int k = 0; k < 5; k++) {
        float g = c_g[k];
        mu1 += g*U.m[0][ty+k][tx];
        mu2 += g*U.m[1][ty+k][tx];
        x11 += g*U.m[2][ty+k][tx];
        x22 += g*U.m[3][ty+k][tx];
        x12 += g*U.m[4][ty+k][tx];
    }

    float s1  = x11 - mu1*mu1;
    float s2  = x22 - mu2*mu2;
    float s12 = x12 - mu1*mu2;
    const float C1 = 1e-4f, C2 = 9e-4f;
    float den  = s1 + s2 + C2;
    float num2 = 2.f*s12 + C2;
    oC = num2 / den;
    oS = ((2.f*mu1*mu2 + C1) * num2) / ((mu1*mu1 + mu2*mu2 + C1) * den);

    if (pool && ut < 64) {
        int rp = ut >> 4, cp = ut & 15;
        int Ho = Hl >> 1;
        float p1 = 0.25f*(U.t1[2*rp+2][2*cp+2] + U.t1[2*rp+2][2*cp+3] +
                          U.t1[2*rp+3][2*cp+2] + U.t1[2*rp+3][2*cp+3]);
        float p2 = 0.25f*(U.t2[2*rp+2][2*cp+2] + U.t2[2*rp+2][2*cp+3] +
                          U.t2[2*rp+3][2*cp+2] + U.t2[2*rp+3][2*cp+3]);
        size_t o = (size_t)offo + (size_t)b*Ho*Ho + (size_t)((oy>>1)+rp)*Ho + (ox>>1)+cp;
        d_Lp[o] = p1;
        d_Lt[o] = p2;
    }
    __syncthreads();   // protect t1/t2/m before next tile's load
}

// ---------------- standalone SSIM kernel (levels 0, 1) ----------------------
__global__ void k_ssim(unsigned off, unsigned offo, int Hl, int lvl)
{
    __shared__ Unit U;
    int b  = blockIdx.z;
    int ut = threadIdx.y*32 + threadIdx.x;

    float vs, vc;
    ssim_tile(U, ut, off, offo, Hl, b, blockIdx.x, blockIdx.y, true, vs, vc);

    for (int o = 16; o; o >>= 1) {
        vs += __shfl_down_sync(0xffffffffu, vs, o);
        vc += __shfl_down_sync(0xffffffffu, vc, o);
    }
    int lane = ut & 31, wid = ut >> 5;
    if (lane == 0) { U.redS[wid] = vs; U.redC[wid] = vc; }
    __syncthreads();
    if (wid == 0) {
        vs = (lane < 8) ? U.redS[lane] : 0.f;
        vc = (lane < 8) ? U.redC[lane] : 0.f;
        for (int o = 4; o; o >>= 1) {
            vs += __shfl_down_sync(0xffffffffu, vs, o);
            vc += __shfl_down_sync(0xffffffffu, vc, o);
        }
        if (lane == 0) {
            atomicAdd(&d_ssim_sum[b*5 + lvl], vs);
            atomicAdd(&d_cs_sum[b*5 + lvl], vc);
        }
    }
}

// ---------------- tail: levels 2,3,4 + final assembly ------------------------
// 8 blocks x 1024 threads; block b owns image b. Last block out does the final.
__global__ void __launch_bounds__(1024, 1)
k_tail(float* __restrict__ out)
{
    __shared__ Unit Us[4];
    __shared__ float rS[32], rC[32];
    __shared__ float l1img[8], msarr[8];
    __shared__ unsigned rank_s;

    int tid  = threadIdx.x;
    int ublk = tid >> 8;
    int ut   = tid & 255;
    int b    = blockIdx.x;
    Unit& U  = Us[ublk];
    int lane = tid & 31, wid = tid >> 5;

    const int      iters[3] = {16, 4, 1};
    const int      Hls[3]   = {128, 64, 32};
    const unsigned offi[3]  = {OFF2, OFF3, OFF4};
    const unsigned offo_[3] = {OFF3, OFF4, 0};

#pragma unroll
    for (int lv = 0; lv < 3; lv++) {
        int Hl = Hls[lv];
        int tpx = Hl >> 5;
        bool pool = (lv < 2);
        float aS = 0.f, aC = 0.f;
        for (int i = 0; i < iters[lv]; i++) {
            int t = ublk + i*4;
            float vs, vc;
            ssim_tile(U, ut, offi[lv], offo_[lv], Hl, b, t % tpx, t / tpx, pool, vs, vc);
            aS += vs; aC += vc;
        }
        // block-wide reduce (1024 threads)
        for (int o = 16; o; o >>= 1) {
            aS += __shfl_down_sync(0xffffffffu, aS, o);
            aC += __shfl_down_sync(0xffffffffu, aC, o);
        }
        if (lane == 0) { rS[wid] = aS; rC[wid] = aC; }
        __syncthreads();
        if (wid == 0) {
            aS = rS[lane]; aC = rC[lane];
            for (int o = 16; o; o >>= 1) {
                aS += __shfl_down_sync(0xffffffffu, aS, o);
                aC += __shfl_down_sync(0xffffffffu, aC, o);
            }
            if (lane == 0) {
                d_ssim_sum[b*5 + 2 + lv] = aS;
                d_cs_sum[b*5 + 2 + lv]   = aC;
            }
        }
        __syncthreads();
    }

    // -------- elect last block --------
    if (tid == 0) {
        __threadfence();
        rank_s = atomicAdd(&g_done, 1u);
    }
    __syncthreads();
    if (rank_s != Bn - 1) return;
    __threadfence();    // acquire other blocks' global writes

    // -------- final assembly (this block only) --------
    if (tid < 256) {
        int ib = tid >> 5, l2 = tid & 31;
        float s = 0.f;
        for (int i = l2; i < 3*NBINS; i += 32) {
            int d = d_histp[ib*3*NBINS + i] - d_histt[ib*3*NBINS + i];
            s += fabsf((float)d);
        }
        for (int o = 16; o; o >>= 1) s += __shfl_down_sync(0xffffffffu, s, o);
        if (l2 == 0) l1img[ib] = s * (1.f/768.f);
    }
    __syncthreads();

    if (tid < 8) {
        const float wts[5] = {0.0448f, 0.2856f, 0.3001f, 0.2363f, 0.1333f};
        const float cnt[5] = {262144.f, 65536.f, 16384.f, 4096.f, 1024.f};
        float ms = 1.f;
        for (int l = 0; l < 4; l++) {
            float mcs = d_cs_sum[tid*5 + l] / cnt[l];
            ms *= powf((mcs + 1.f)*0.5f, wts[l]);
        }
        float mss4 = d_ssim_sum[tid*5 + 4] / cnt[4];
        ms *= powf((mss4 + 1.f)*0.5f, wts[4]);
        msarr[tid] = 1.f - ms;
    }
    __syncthreads();

    if (tid == 0) {
        float hist_loss = 0.f;
        for (int i = 0; i < 8; i++)
            hist_loss += exp2f((float)(i - 8)) * (l1img[i] + 1.f);
        float scaler = (float)NPIX / 20.f;
        hist_loss = hist_loss / 8.f / scaler;
        float lab_l1 = d_l1sum / (float)(Bn*3*NPIX);
        float sl = 0.f;
        for (int i = 0; i < 8; i++) sl += msarr[i];
        sl *= (1.f/8.f);
        out[0] = lab_l1 + hist_loss;
        out[1] = sl;
    }
    __syncthreads();

    // -------- re-zero state for next graph replay --------
    for (int i = tid; i < Bn*3*NBINS; i += 1024) { d_histp[i] = 0; d_histt[i] = 0; }
    if (tid < Bn*5) { d_ssim_sum[tid] = 0.f; d_cs_sum[tid] = 0.f; }
    if (tid == 0) { d_l1sum = 0.f; g_done = 0u; __threadfence(); }
}

// ---------------- launch ----------------------------------------------------
extern "C" void kernel_launch(void* const* d_in, const int* in_sizes, int n_in,
                              void* d_out, int out_size)
{
    const float* pred = (const float*)d_in[1];
    const float* tgt  = (const float*)d_in[2];
    float* out = (float*)d_out;

    dim3 g1(128, Bn);
    k_lab<<<g1, 256>>>(pred, tgt);

    dim3 blk(32, 8);
    k_ssim<<<dim3(16, 64, Bn), blk>>>(OFF0, OFF1, 512, 0);
    k_ssim<<<dim3(8, 32, Bn),  blk>>>(OFF1, OFF2, 256, 1);

    k_tail<<<Bn, 1024>>>(out);
}

// round 5
// speedup vs baseline: 1.3933x; 1.3831x over previous
#include <cuda_runtime.h>
#include <math.h>

#define Bn    8
#define NPIX  (512*512)
#define NBINS 256

#define OFF0 0u
#define OFF1 2097152u
#define OFF2 2621440u
#define OFF3 2752512u
#define OFF4 2785280u

#define G0 0.12007823f
#define G1 0.23388087f
#define G2 0.29208180f
__device__ __constant__ float c_g[5] = {G0, G1, G2, G1, G0};

__device__ float d_Lp[2793472];
__device__ float d_Lt[2793472];
__device__ int   d_histd[Bn*3*NBINS];      // signed: pred-count minus tgt-count
__device__ float d_l1sum;
__device__ float d_ssim_sum[Bn*5];
__device__ float d_cs_sum[Bn*5];
__device__ unsigned g_img_done[Bn];
__device__ unsigned g_final;

__device__ __forceinline__ void bar_sync(int id)
{
    asm volatile("bar.sync %0, 256;" :: "r"(id) : "memory");
}

// ---------------- RGB -> normalized LAB -------------------------------------
__device__ __forceinline__ float srgb_lin(float x)
{
    if (x <= 0.04045f) return x * (1.f/12.92f);
    float y = (fmaxf(x, 1e-4f) + 0.055f) * (1.f/1.055f);
    return __powf(y, 2.4f);
}

__device__ __forceinline__ float f_lab(float t)
{
    const float e3 = 0.008856451679035631f;
    if (t <= e3) return t * (841.f/108.f) + (4.f/29.f);
    return __powf(fmaxf(t, 1e-4f), 1.f/3.f);
}

__device__ __forceinline__ void rgb2lab_norm(float r, float g, float b,
                                             float& L, float& A, float& Bc)
{
    float lr = srgb_lin(r), lg = srgb_lin(g), lb = srgb_lin(b);
    float X = lr*0.412453f + lg*0.357580f + lb*0.180423f;
    float Y = lr*0.212671f + lg*0.715160f + lb*0.072169f;
    float Z = lr*0.019334f + lg*0.119193f + lb*0.950227f;
    X *= (1.f/0.950456f);
    Z *= (1.f/1.088754f);
    float fx = f_lab(X), fy = f_lab(Y), fz = f_lab(Z);
    float Ll = 116.f*fy - 16.f;
    float Aa = 500.f*(fx - fy);
    float Bb = 200.f*(fy - fz);
    L  = fminf(fmaxf(Ll * 0.01f,                 0.f), 1.f);
    A  = fminf(fmaxf((Aa*(1.f/110.f)+1.f)*0.5f,  0.f), 1.f);
    Bc = fminf(fmaxf((Bb*(1.f/110.f)+1.f)*0.5f,  0.f), 1.f);
}

__device__ __forceinline__ int bin_of(float v)
{
    int b = (int)(v * 256.f);
    return b > 255 ? 255 : b;
}

// ---------------- fused LAB + signed histogram + L1 + L store ---------------
// grid (128, 8) x 256 threads; 8 px/thread (2 float4 iters)
__global__ void k_lab(const float* __restrict__ pred, const float* __restrict__ tgt)
{
    __shared__ int   sh[3*NBINS];
    __shared__ float red[8];
    int b   = blockIdx.y;
    int tid = threadIdx.x;

    for (int i = tid; i < 3*NBINS; i += 256) sh[i] = 0;
    __syncthreads();

    const size_t ibase = (size_t)b*3*NPIX;
    float l1acc = 0.f;

#pragma unroll
    for (int it = 0; it < 2; it++) {
        int p = blockIdx.x*2048 + it*1024 + tid*4;
        float4 pr = *(const float4*)(pred + ibase + p);
        float4 pg = *(const float4*)(pred + ibase + NPIX + p);
        float4 pb = *(const float4*)(pred + ibase + 2*NPIX + p);
        float4 tr = *(const float4*)(tgt  + ibase + p);
        float4 tg = *(const float4*)(tgt  + ibase + NPIX + p);
        float4 tb = *(const float4*)(tgt  + ibase + 2*NPIX + p);

        float4 plo, tlo;
        float* prf = &pr.x; float* pgf = &pg.x; float* pbf = &pb.x;
        float* trf = &tr.x; float* tgf = &tg.x; float* tbf = &tb.x;
        float* plf = &plo.x; float* tlf = &tlo.x;
#pragma unroll
        for (int j = 0; j < 4; j++) {
            float pl, pa, pbc, tl, ta, tbc;
            rgb2lab_norm(prf[j], pgf[j], pbf[j], pl, pa, pbc);
            rgb2lab_norm(trf[j], tgf[j], tbf[j], tl, ta, tbc);
            plf[j] = pl; tlf[j] = tl;
            atomicAdd(&sh[0*NBINS + bin_of(pl)],   1);
            atomicAdd(&sh[1*NBINS + bin_of(pa)],   1);
            atomicAdd(&sh[2*NBINS + bin_of(pbc)],  1);
            atomicAdd(&sh[0*NBINS + bin_of(tl)],  -1);
            atomicAdd(&sh[1*NBINS + bin_of(ta)],  -1);
            atomicAdd(&sh[2*NBINS + bin_of(tbc)], -1);
            l1acc += fabsf(pl-tl) + fabsf(pa-ta) + fabsf(pbc-tbc);
        }
        *(float4*)(d_Lp + (size_t)b*NPIX + p) = plo;
        *(float4*)(d_Lt + (size_t)b*NPIX + p) = tlo;
    }
    __syncthreads();

    for (int i = tid; i < 3*NBINS; i += 256) {
        int hd = sh[i];
        if (hd) atomicAdd(&d_histd[b*3*NBINS + i], hd);
    }

    float v = l1acc;
    for (int o = 16; o; o >>= 1) v += __shfl_down_sync(0xffffffffu, v, o);
    int lane = tid & 31, wid = tid >> 5;
    if (lane == 0) red[wid] = v;
    __syncthreads();
    if (wid == 0) {
        v = (lane < 8) ? red[lane] : 0.f;
        for (int o = 4; o; o >>= 1) v += __shfl_down_sync(0xffffffffu, v, o);
        if (lane == 0) atomicAdd(&d_l1sum, v);
    }
}

// ---------------- SSIM tile machinery ---------------------------------------
struct Unit {
    float t1[12][36];
    float t2[12][36];
    float m[5][12][32];
    float redS[8], redC[8];
};

// One 32x8 output tile per 256-thread unit; syncs with named barrier `bar`.
__device__ __forceinline__ void ssim_tile(Unit& U, int ut, int bar,
                                          unsigned off, unsigned offo,
                                          int Hl, int b, int tix, int tiy,
                                          bool pool, float& oS, float& oC)
{
    const float* i1 = d_Lp + off + (size_t)b*Hl*Hl;
    const float* i2 = d_Lt + off + (size_t)b*Hl*Hl;
    int ox = tix*32, oy = tiy*8;

    for (int i = ut; i < 12*36; i += 256) {
        int r = i/36, c = i%36;
        int gy = oy + r - 2, gx = ox + c - 2;
        float v1 = 0.f, v2 = 0.f;
        if (gy >= 0 && gy < Hl && gx >= 0 && gx < Hl) {
            v1 = i1[gy*Hl + gx];
            v2 = i2[gy*Hl + gx];
        }
        U.t1[r][c] = v1;
        U.t2[r][c] = v2;
    }
    bar_sync(bar);

    for (int i = ut; i < 12*32; i += 256) {
        int r = i >> 5, c = i & 31;
        float m1 = 0.f, m2 = 0.f, a11 = 0.f, a22 = 0.f, a12 = 0.f;
#pragma unroll
        for (int k = 0; k < 5; k++) {
            float g = c_g[k];
            float a = U.t1[r][c+k];
            float q = U.t2[r][c+k];
            float ga = g*a, gq = g*q;
            m1 += ga;  m2 += gq;
            a11 += ga*a; a22 += gq*q; a12 += ga*q;
        }
        U.m[0][r][c] = m1; U.m[1][r][c] = m2;
        U.m[2][r][c] = a11; U.m[3][r][c] = a22; U.m[4][r][c] = a12;
    }
    bar_sync(bar);

    int tx = ut & 31, ty = ut >> 5;
    float mu1 = 0.f, mu2 = 0.f, x11 = 0.f, x22 = 0.f, x12 = 0.f;
#pragma unroll
    for (int k = 0; k < 5; k++) {
        float g = c_g[k];
        mu1 += g*U.m[0][ty+k][tx];
        mu2 += g*U.m[1][ty+k][tx];
        x11 += g*U.m[2][ty+k][tx];
        x22 += g*U.m[3][ty+k][tx];
        x12 += g*U.m[4][ty+k][tx];
    }

    float s1  = x11 - mu1*mu1;
    float s2  = x22 - mu2*mu2;
    float s12 = x12 - mu1*mu2;
    const float C1 = 1e-4f, C2 = 9e-4f;
    float den  = s1 + s2 + C2;
    float num2 = 2.f*s12 + C2;
    oC = num2 / den;
    oS = ((2.f*mu1*mu2 + C1) * num2) / ((mu1*mu1 + mu2*mu2 + C1) * den);

    if (pool && ut < 64) {
        int rp = ut >> 4, cp = ut & 15;
        int Ho = Hl >> 1;
        float p1 = 0.25f*(U.t1[2*rp+2][2*cp+2] + U.t1[2*rp+2][2*cp+3] +
                          U.t1[2*rp+3][2*cp+2] + U.t1[2*rp+3][2*cp+3]);
        float p2 = 0.25f*(U.t2[2*rp+2][2*cp+2] + U.t2[2*rp+2][2*cp+3] +
                          U.t2[2*rp+3][2*cp+2] + U.t2[2*rp+3][2*cp+3]);
        size_t o = (size_t)offo + (size_t)b*Ho*Ho + (size_t)((oy>>1)+rp)*Ho + (ox>>1)+cp;
        d_Lp[o] = p1;
        d_Lt[o] = p2;
    }
    bar_sync(bar);   // protect t1/t2/m before next round's load
}

// ---------------- standalone SSIM kernel (levels 0, 1) ----------------------
__global__ void k_ssim(unsigned off, unsigned offo, int Hl, int lvl)
{
    __shared__ Unit U;
    int b  = blockIdx.z;
    int ut = threadIdx.y*32 + threadIdx.x;

    float vs, vc;
    ssim_tile(U, ut, 0, off, offo, Hl, b, blockIdx.x, blockIdx.y, true, vs, vc);

    for (int o = 16; o; o >>= 1) {
        vs += __shfl_down_sync(0xffffffffu, vs, o);
        vc += __shfl_down_sync(0xffffffffu, vc, o);
    }
    int lane = ut & 31, wid = ut >> 5;
    if (lane == 0) { U.redS[wid] = vs; U.redC[wid] = vc; }
    __syncthreads();
    if (wid == 0) {
        vs = (lane < 8) ? U.redS[lane] : 0.f;
        vc = (lane < 8) ? U.redC[lane] : 0.f;
        for (int o = 4; o; o >>= 1) {
            vs += __shfl_down_sync(0xffffffffu, vs, o);
            vc += __shfl_down_sync(0xffffffffu, vc, o);
        }
        if (lane == 0) {
            atomicAdd(&d_ssim_sum[b*5 + lvl], vs);
            atomicAdd(&d_cs_sum[b*5 + lvl], vc);
        }
    }
}

// ---------------- block-wide (1024 thr) pair reduce; result in thread 0 -----
__device__ __forceinline__ void breduce(float& a, float& c,
                                        float* rS, float* rC, int lane, int wid)
{
    for (int o = 16; o; o >>= 1) {
        a += __shfl_down_sync(0xffffffffu, a, o);
        c += __shfl_down_sync(0xffffffffu, c, o);
    }
    if (lane == 0) { rS[wid] = a; rC[wid] = c; }
    __syncthreads();
    if (wid == 0) {
        a = rS[lane]; c = rC[lane];
        for (int o = 16; o; o >>= 1) {
            a += __shfl_down_sync(0xffffffffu, a, o);
            c += __shfl_down_sync(0xffffffffu, c, o);
        }
    }
    __syncthreads();   // rS/rC reusable
}

// ---------------- tail: L2 wide + elected L3/L4 + final ----------------------
// 128 blocks x 1024 threads (16 blocks per image, 4 units per block)
__global__ void __launch_bounds__(1024, 1)
k_tail(float* __restrict__ out)
{
    __shared__ Unit Us[4];
    __shared__ float rS[32], rC[32];
    __shared__ float l1img[8], msarr[8];
    __shared__ unsigned rank_s;

    int tid  = threadIdx.x;
    int ublk = tid >> 8;
    int ut   = tid & 255;
    int lane = tid & 31, wid = tid >> 5;
    int img  = blockIdx.x >> 4;
    int sub  = blockIdx.x & 15;
    Unit& U  = Us[ublk];
    int bar  = 1 + ublk;

    // -------- L2: 64 tiles/img, 16 blocks x 4 units -> 1 round --------------
    {
        int t = sub*4 + ublk;            // 0..63
        float vs, vc;
        ssim_tile(U, ut, bar, OFF2, OFF3, 128, img, t & 3, t >> 2, true, vs, vc);
        breduce(vs, vc, rS, rC, lane, wid);
        if (tid == 0) {
            atomicAdd(&d_ssim_sum[img*5 + 2], vs);
            atomicAdd(&d_cs_sum[img*5 + 2], vc);
        }
    }
    __syncthreads();

    // -------- elect last block of this image --------------------------------
    if (tid == 0) {
        __threadfence();
        rank_s = atomicAdd(&g_img_done[img], 1u);
    }
    __syncthreads();
    if (rank_s != 15u) return;
    __threadfence();                     // acquire peers' L3 pool writes

    // -------- L3: 16 tiles, 4 units -> 4 rounds ------------------------------
    {
        float aS = 0.f, aC = 0.f;
        for (int r = 0; r < 4; r++) {
            int t = ublk + r*4;          // 0..15
            float vs, vc;
            ssim_tile(U, ut, bar, OFF3, OFF4, 64, img, t & 1, t >> 1, true, vs, vc);
            aS += vs; aC += vc;
        }
        breduce(aS, aC, rS, rC, lane, wid);
        if (tid == 0) {
            d_ssim_sum[img*5 + 3] = aS;
            d_cs_sum[img*5 + 3]   = aC;
        }
    }
    __syncthreads();                     // L4 region writes visible block-wide

    // -------- L4: 4 tiles, 1 round ------------------------------------------
    {
        float vs, vc;
        ssim_tile(U, ut, bar, OFF4, 0, 32, img, 0, ublk, false, vs, vc);
        breduce(vs, vc, rS, rC, lane, wid);
        if (tid == 0) {
            d_ssim_sum[img*5 + 4] = vs;
            d_cs_sum[img*5 + 4]   = vc;
        }
    }
    __syncthreads();

    // -------- global elect among the 8 image-winners -------------------------
    if (tid == 0) {
        __threadfence();
        rank_s = atomicAdd(&g_final, 1u);
    }
    __syncthreads();
    if (rank_s != (unsigned)(Bn - 1)) return;
    __threadfence();                     // acquire other winners' sums

    // -------- final assembly --------------------------------------------------
    if (tid < 256) {
        int ib = tid >> 5, l2 = tid & 31;
        float s = 0.f;
        for (int i = l2; i < 3*NBINS; i += 32)
            s += fabsf((float)d_histd[ib*3*NBINS + i]);
        for (int o = 16; o; o >>= 1) s += __shfl_down_sync(0xffffffffu, s, o);
        if (l2 == 0) l1img[ib] = s * (1.f/768.f);
    }
    __syncthreads();

    if (tid < 8) {
        const float wts[5] = {0.0448f, 0.2856f, 0.3001f, 0.2363f, 0.1333f};
        const float cnt[5] = {262144.f, 65536.f, 16384.f, 4096.f, 1024.f};
        float ms = 1.f;
        for (int l = 0; l < 4; l++) {
            float mcs = d_cs_sum[tid*5 + l] / cnt[l];
            ms *= powf((mcs + 1.f)*0.5f, wts[l]);
        }
        float mss4 = d_ssim_sum[tid*5 + 4] / cnt[4];
        ms *= powf((mss4 + 1.f)*0.5f, wts[4]);
        msarr[tid] = 1.f - ms;
    }
    __syncthreads();

    if (tid == 0) {
        float hist_loss = 0.f;
        for (int i = 0; i < 8; i++)
            hist_loss += exp2f((float)(i - 8)) * (l1img[i] + 1.f);
        float scaler = (float)NPIX / 20.f;
        hist_loss = hist_loss / 8.f / scaler;
        float lab_l1 = d_l1sum / (float)(Bn*3*NPIX);
        float sl = 0.f;
        for (int i = 0; i < 8; i++) sl += msarr[i];
        sl *= (1.f/8.f);
        out[0] = lab_l1 + hist_loss;
        out[1] = sl;
    }
    __syncthreads();

    // -------- re-zero all state for next graph replay -------------------------
    for (int i = tid; i < Bn*3*NBINS; i += 1024) d_histd[i] = 0;
    if (tid < Bn*5) { d_ssim_sum[tid] = 0.f; d_cs_sum[tid] = 0.f; }
    if (tid < Bn)   g_img_done[tid] = 0u;
    if (tid == 0) { d_l1sum = 0.f; g_final = 0u; __threadfence(); }
}

// ---------------- launch ------------------------------------------------------
extern "C" void kernel_launch(void* const* d_in, const int* in_sizes, int n_in,
                              void* d_out, int out_size)
{
    const float* pred = (const float*)d_in[1];
    const float* tgt  = (const float*)d_in[2];
    float* out = (float*)d_out;

    dim3 g1(128, Bn);
    k_lab<<<g1, 256>>>(pred, tgt);

    dim3 blk(32, 8);
    k_ssim<<<dim3(16, 64, Bn), blk>>>(OFF0, OFF1, 512, 0);
    k_ssim<<<dim3(8, 32, Bn),  blk>>>(OFF1, OFF2, 256, 1);

    k_tail<<<128, 1024>>>(out);
}

// round 7
// speedup vs baseline: 1.5113x; 1.0847x over previous
#include <cuda_runtime.h>
#include <math.h>

#define Bn    8
#define NPIX  (512*512)
#define NBINS 256

#define OFF0 0u
#define OFF1 2097152u
#define OFF2 2621440u
#define OFF3 2752512u
#define OFF4 2785280u

#define G0 0.12007823f
#define G1 0.23388087f
#define G2 0.29208180f
__device__ __constant__ float c_g[5] = {G0, G1, G2, G1, G0};

__device__ float d_Lp[2793472];
__device__ float d_Lt[2793472];
__device__ int   d_histd[Bn*3*NBINS];      // signed: pred-count minus tgt-count
__device__ float d_l1sum;
__device__ float d_ssim_sum[Bn*5];
__device__ float d_cs_sum[Bn*5];
__device__ float d_l1img[Bn];
__device__ unsigned g_img_done[Bn];
__device__ unsigned g_img2[Bn];
__device__ unsigned g_final;

__device__ __forceinline__ void bar_sync(int id)
{
    asm volatile("bar.sync %0, 256;" :: "r"(id) : "memory");
}

__device__ __forceinline__ unsigned ld_cg(const unsigned* p)
{
    unsigned v;
    asm volatile("ld.global.cg.u32 %0, [%1];" : "=r"(v) : "l"(p) : "memory");
    return v;
}

// ---------------- RGB -> normalized LAB -------------------------------------
__device__ __forceinline__ float srgb_lin(float x)
{
    if (x <= 0.04045f) return x * (1.f/12.92f);
    float y = (fmaxf(x, 1e-4f) + 0.055f) * (1.f/1.055f);
    return __powf(y, 2.4f);
}

__device__ __forceinline__ float f_lab(float t)
{
    const float e3 = 0.008856451679035631f;
    if (t <= e3) return t * (841.f/108.f) + (4.f/29.f);
    return __powf(fmaxf(t, 1e-4f), 1.f/3.f);
}

__device__ __forceinline__ void rgb2lab_norm(float r, float g, float b,
                                             float& L, float& A, float& Bc)
{
    float lr = srgb_lin(r), lg = srgb_lin(g), lb = srgb_lin(b);
    float X = lr*0.412453f + lg*0.357580f + lb*0.180423f;
    float Y = lr*0.212671f + lg*0.715160f + lb*0.072169f;
    float Z = lr*0.019334f + lg*0.119193f + lb*0.950227f;
    X *= (1.f/0.950456f);
    Z *= (1.f/1.088754f);
    float fx = f_lab(X), fy = f_lab(Y), fz = f_lab(Z);
    float Ll = 116.f*fy - 16.f;
    float Aa = 500.f*(fx - fy);
    float Bb = 200.f*(fy - fz);
    L  = fminf(fmaxf(Ll * 0.01f,                 0.f), 1.f);
    A  = fminf(fmaxf((Aa*(1.f/110.f)+1.f)*0.5f,  0.f), 1.f);
    Bc = fminf(fmaxf((Bb*(1.f/110.f)+1.f)*0.5f,  0.f), 1.f);
}

__device__ __forceinline__ int bin_of(float v)
{
    int b = (int)(v * 256.f);
    return b > 255 ? 255 : b;
}

// ---------------- fused LAB + signed histogram + L1 + L store ---------------
// grid (128, 8) x 256 threads; 8 px/thread (2 float4 iters)
__global__ void k_lab(const float* __restrict__ pred, const float* __restrict__ tgt)
{
    __shared__ int   sh[3*NBINS];
    __shared__ float red[8];
    int b   = blockIdx.y;
    int tid = threadIdx.x;

    for (int i = tid; i < 3*NBINS; i += 256) sh[i] = 0;
    __syncthreads();

    const size_t ibase = (size_t)b*3*NPIX;
    float l1acc = 0.f;

#pragma unroll
    for (int it = 0; it < 2; it++) {
        int p = blockIdx.x*2048 + it*1024 + tid*4;
        float4 pr = *(const float4*)(pred + ibase + p);
        float4 pg = *(const float4*)(pred + ibase + NPIX + p);
        float4 pb = *(const float4*)(pred + ibase + 2*NPIX + p);
        float4 tr = *(const float4*)(tgt  + ibase + p);
        float4 tg = *(const float4*)(tgt  + ibase + NPIX + p);
        float4 tb = *(const float4*)(tgt  + ibase + 2*NPIX + p);

        float4 plo, tlo;
        float* prf = &pr.x; float* pgf = &pg.x; float* pbf = &pb.x;
        float* trf = &tr.x; float* tgf = &tg.x; float* tbf = &tb.x;
        float* plf = &plo.x; float* tlf = &tlo.x;
#pragma unroll
        for (int j = 0; j < 4; j++) {
            float pl, pa, pbc, tl, ta, tbc;
            rgb2lab_norm(prf[j], pgf[j], pbf[j], pl, pa, pbc);
            rgb2lab_norm(trf[j], tgf[j], tbf[j], tl, ta, tbc);
            plf[j] = pl; tlf[j] = tl;
            atomicAdd(&sh[0*NBINS + bin_of(pl)],   1);
            atomicAdd(&sh[1*NBINS + bin_of(pa)],   1);
            atomicAdd(&sh[2*NBINS + bin_of(pbc)],  1);
            atomicAdd(&sh[0*NBINS + bin_of(tl)],  -1);
            atomicAdd(&sh[1*NBINS + bin_of(ta)],  -1);
            atomicAdd(&sh[2*NBINS + bin_of(tbc)], -1);
            l1acc += fabsf(pl-tl) + fabsf(pa-ta) + fabsf(pbc-tbc);
        }
        *(float4*)(d_Lp + (size_t)b*NPIX + p) = plo;
        *(float4*)(d_Lt + (size_t)b*NPIX + p) = tlo;
    }
    __syncthreads();

    for (int i = tid; i < 3*NBINS; i += 256) {
        int hd = sh[i];
        if (hd) atomicAdd(&d_histd[b*3*NBINS + i], hd);
    }

    float v = l1acc;
    for (int o = 16; o; o >>= 1) v += __shfl_down_sync(0xffffffffu, v, o);
    int lane = tid & 31, wid = tid >> 5;
    if (lane == 0) red[wid] = v;
    __syncthreads();
    if (wid == 0) {
        v = (lane < 8) ? red[lane] : 0.f;
        for (int o = 4; o; o >>= 1) v += __shfl_down_sync(0xffffffffu, v, o);
        if (lane == 0) atomicAdd(&d_l1sum, v);
    }
}

// ---------------- SSIM tile machinery ---------------------------------------
struct Unit {
    float t1[12][36];
    float t2[12][36];
    float m[5][12][32];
    float redS[8], redC[8];
};

// One 32x8 output tile per 256-thread unit; syncs with named barrier `bar`.
__device__ __forceinline__ void ssim_tile(Unit& U, int ut, int bar,
                                          unsigned off, unsigned offo,
                                          int Hl, int b, int tix, int tiy,
                                          bool pool, float& oS, float& oC)
{
    const float* i1 = d_Lp + off + (size_t)b*Hl*Hl;
    const float* i2 = d_Lt + off + (size_t)b*Hl*Hl;
    int ox = tix*32, oy = tiy*8;

    for (int i = ut; i < 12*36; i += 256) {
        int r = i/36, c = i%36;
        int gy = oy + r - 2, gx = ox + c - 2;
        float v1 = 0.f, v2 = 0.f;
        if (gy >= 0 && gy < Hl && gx >= 0 && gx < Hl) {
            v1 = i1[gy*Hl + gx];
            v2 = i2[gy*Hl + gx];
        }
        U.t1[r][c] = v1;
        U.t2[r][c] = v2;
    }
    bar_sync(bar);

    for (int i = ut; i < 12*32; i += 256) {
        int r = i >> 5, c = i & 31;
        float m1 = 0.f, m2 = 0.f, a11 = 0.f, a22 = 0.f, a12 = 0.f;
#pragma unroll
        for (int k = 0; k < 5; k++) {
            float g = c_g[k];
            float a = U.t1[r][c+k];
            float q = U.t2[r][c+k];
            float ga = g*a, gq = g*q;
            m1 += ga;  m2 += gq;
            a11 += ga*a; a22 += gq*q; a12 += ga*q;
        }
        U.m[0][r][c] = m1; U.m[1][r][c] = m2;
        U.m[2][r][c] = a11; U.m[3][r][c] = a22; U.m[4][r][c] = a12;
    }
    bar_sync(bar);

    int tx = ut & 31, ty = ut >> 5;
    float mu1 = 0.f, mu2 = 0.f, x11 = 0.f, x22 = 0.f, x12 = 0.f;
#pragma unroll
    for (int k = 0; k < 5; k++) {
        float g = c_g[k];
        mu1 += g*U.m[0][ty+k][tx];
        mu2 += g*U.m[1][ty+k][tx];
        x11 += g*U.m[2][ty+k][tx];
        x22 += g*U.m[3][ty+k][tx];
        x12 += g*U.m[4][ty+k][tx];
    }

    float s1  = x11 - mu1*mu1;
    float s2  = x22 - mu2*mu2;
    float s12 = x12 - mu1*mu2;
    const float C1 = 1e-4f, C2 = 9e-4f;
    float den  = s1 + s2 + C2;
    float num2 = 2.f*s12 + C2;
    oC = num2 / den;
    oS = ((2.f*mu1*mu2 + C1) * num2) / ((mu1*mu1 + mu2*mu2 + C1) * den);

    if (pool && ut < 64) {
        int rp = ut >> 4, cp = ut & 15;
        int Ho = Hl >> 1;
        float p1 = 0.25f*(U.t1[2*rp+2][2*cp+2] + U.t1[2*rp+2][2*cp+3] +
                          U.t1[2*rp+3][2*cp+2] + U.t1[2*rp+3][2*cp+3]);
        float p2 = 0.25f*(U.t2[2*rp+2][2*cp+2] + U.t2[2*rp+2][2*cp+3] +
                          U.t2[2*rp+3][2*cp+2] + U.t2[2*rp+3][2*cp+3]);
        size_t o = (size_t)offo + (size_t)b*Ho*Ho + (size_t)((oy>>1)+rp)*Ho + (ox>>1)+cp;
        d_Lp[o] = p1;
        d_Lt[o] = p2;
    }
    bar_sync(bar);   // protect t1/t2/m before next round's load
}

// ---------------- standalone SSIM kernel (levels 0, 1) ----------------------
__global__ void k_ssim(unsigned off, unsigned offo, int Hl, int lvl)
{
    __shared__ Unit U;
    int b  = blockIdx.z;
    int ut = threadIdx.y*32 + threadIdx.x;

    float vs, vc;
    ssim_tile(U, ut, 0, off, offo, Hl, b, blockIdx.x, blockIdx.y, true, vs, vc);

    for (int o = 16; o; o >>= 1) {
        vs += __shfl_down_sync(0xffffffffu, vs, o);
        vc += __shfl_down_sync(0xffffffffu, vc, o);
    }
    int lane = ut & 31, wid = ut >> 5;
    if (lane == 0) { U.redS[wid] = vs; U.redC[wid] = vc; }
    __syncthreads();
    if (wid == 0) {
        vs = (lane < 8) ? U.redS[lane] : 0.f;
        vc = (lane < 8) ? U.redC[lane] : 0.f;
        for (int o = 4; o; o >>= 1) {
            vs += __shfl_down_sync(0xffffffffu, vs, o);
            vc += __shfl_down_sync(0xffffffffu, vc, o);
        }
        if (lane == 0) {
            atomicAdd(&d_ssim_sum[b*5 + lvl], vs);
            atomicAdd(&d_cs_sum[b*5 + lvl], vc);
        }
    }
}

// ---------------- block-wide (1024 thr) pair reduce; result in thread 0 -----
__device__ __forceinline__ void breduce(float& a, float& c,
                                        float* rS, float* rC, int lane, int wid)
{
    for (int o = 16; o; o >>= 1) {
        a += __shfl_down_sync(0xffffffffu, a, o);
        c += __shfl_down_sync(0xffffffffu, c, o);
    }
    if (lane == 0) { rS[wid] = a; rC[wid] = c; }
    __syncthreads();
    if (wid == 0) {
        a = rS[lane]; c = rC[lane];
        for (int o = 16; o; o >>= 1) {
            a += __shfl_down_sync(0xffffffffu, a, o);
            c += __shfl_down_sync(0xffffffffu, c, o);
        }
    }
    __syncthreads();   // rS/rC reusable
}

// ---------------- block-wide (1024 thr) scalar reduce; result in thread 0 ---
__device__ __forceinline__ float breduce1(float a, float* rS, int lane, int wid)
{
    for (int o = 16; o; o >>= 1) a += __shfl_down_sync(0xffffffffu, a, o);
    if (lane == 0) rS[wid] = a;
    __syncthreads();
    if (wid == 0) {
        a = rS[lane];
        for (int o = 16; o; o >>= 1) a += __shfl_down_sync(0xffffffffu, a, o);
    }
    __syncthreads();
    return a;           // valid in thread 0
}

// ---------------- tail: L2 wide + 4-block L3 + 1-block L4 + final ------------
// 128 blocks x 1024 threads (16 blocks per image, 4 units per block)
__global__ void __launch_bounds__(1024, 1)
k_tail(float* __restrict__ out)
{
    __shared__ Unit Us[4];
    __shared__ float rS[32], rC[32];
    __shared__ float msarr[8];
    __shared__ unsigned rank_s;

    int tid  = threadIdx.x;
    int ublk = tid >> 8;
    int ut   = tid & 255;
    int lane = tid & 31, wid = tid >> 5;
    int img  = blockIdx.x >> 4;
    int sub  = blockIdx.x & 15;
    Unit& U  = Us[ublk];
    int bar  = 1 + ublk;

    // -------- L2: 64 tiles/img, 16 blocks x 4 units -> 1 round --------------
    {
        int t = sub*4 + ublk;            // 0..63
        float vs, vc;
        ssim_tile(U, ut, bar, OFF2, OFF3, 128, img, t & 3, t >> 2, true, vs, vc);
        breduce(vs, vc, rS, rC, lane, wid);
        if (tid == 0) {
            atomicAdd(&d_ssim_sum[img*5 + 2], vs);
            atomicAdd(&d_cs_sum[img*5 + 2], vc);
        }
    }
    __syncthreads();

    // -------- elect last 4 blocks of this image ------------------------------
    if (tid == 0) {
        __threadfence();
        rank_s = atomicAdd(&g_img_done[img], 1u);
    }
    __syncthreads();
    if (rank_s < 12u) return;
    // bounded spin: the <=3 non-arrived blocks exit right after their add
    if (tid == 0) {
        while (ld_cg(&g_img_done[img]) < 16u) __nanosleep(64);
    }
    __syncthreads();
    __threadfence();                     // acquire peers' L3 pool writes
    int sub4 = (int)rank_s - 12;         // 0..3

    // -------- L3: 16 tiles, 4 blocks x 4 units -> 1 round --------------------
    {
        int t = sub4*4 + ublk;           // 0..15
        float vs, vc;
        ssim_tile(U, ut, bar, OFF3, OFF4, 64, img, t & 1, t >> 1, true, vs, vc);
        breduce(vs, vc, rS, rC, lane, wid);
        if (tid == 0) {
            atomicAdd(&d_ssim_sum[img*5 + 3], vs);
            atomicAdd(&d_cs_sum[img*5 + 3], vc);
        }
    }
    __syncthreads();

    // -------- elect last of the 4 --------------------------------------------
    if (tid == 0) {
        __threadfence();
        rank_s = atomicAdd(&g_img2[img], 1u);
    }
    __syncthreads();
    if (rank_s != 3u) return;
    __threadfence();                     // acquire peers' L4 pool writes

    // -------- L4: 4 tiles, 4 units -> 1 round --------------------------------
    {
        float vs, vc;
        ssim_tile(U, ut, bar, OFF4, 0, 32, img, 0, ublk, false, vs, vc);
        breduce(vs, vc, rS, rC, lane, wid);
        if (tid == 0) {
            d_ssim_sum[img*5 + 4] = vs;
            d_cs_sum[img*5 + 4]   = vc;
        }
    }

    // -------- this image's histogram L1 (dedicated scalar reduce) ------------
    {
        float s = (tid < 3*NBINS) ? fabsf((float)d_histd[img*3*NBINS + tid]) : 0.f;
        s = breduce1(s, rS, lane, wid);
        if (tid == 0) d_l1img[img] = s * (1.f/768.f);
    }
    __syncthreads();

    // -------- global elect among the 8 image-winners --------------------------
    if (tid == 0) {
        __threadfence();
        rank_s = atomicAdd(&g_final, 1u);
    }
    __syncthreads();
    if (rank_s != (unsigned)(Bn - 1)) return;
    __threadfence();                     // acquire other winners' results

    // -------- final assembly ---------------------------------------------------
    if (tid < 8) {
        const float wts[5] = {0.0448f, 0.2856f, 0.3001f, 0.2363f, 0.1333f};
        const float cnt[5] = {262144.f, 65536.f, 16384.f, 4096.f, 1024.f};
        float ms = 1.f;
        for (int l = 0; l < 4; l++) {
            float mcs = d_cs_sum[tid*5 + l] / cnt[l];
            ms *= powf((mcs + 1.f)*0.5f, wts[l]);
        }
        float mss4 = d_ssim_sum[tid*5 + 4] / cnt[4];
        ms *= powf((mss4 + 1.f)*0.5f, wts[4]);
        msarr[tid] = 1.f - ms;
    }
    __syncthreads();

    if (tid == 0) {
        float hist_loss = 0.f;
        for (int i = 0; i < 8; i++)
            hist_loss += exp2f((float)(i - 8)) * (d_l1img[i] + 1.f);
        float scaler = (float)NPIX / 20.f;
        hist_loss = hist_loss / 8.f / scaler;
        float lab_l1 = d_l1sum / (float)(Bn*3*NPIX);
        float sl = 0.f;
        for (int i = 0; i < 8; i++) sl += msarr[i];
        sl *= (1.f/8.f);
        out[0] = lab_l1 + hist_loss;
        out[1] = sl;
    }
    __syncthreads();

    // -------- re-zero all state for next graph replay --------------------------
    for (int i = tid; i < Bn*3*NBINS; i += 1024) d_histd[i] = 0;
    if (tid < Bn*5) { d_ssim_sum[tid] = 0.f; d_cs_sum[tid] = 0.f; }
    if (tid < Bn)   { g_img_done[tid] = 0u; g_img2[tid] = 0u; }
    if (tid == 0) { d_l1sum = 0.f; g_final = 0u; __threadfence(); }
}

// ---------------- launch ------------------------------------------------------
extern "C" void kernel_launch(void* const* d_in, const int* in_sizes, int n_in,
                              void* d_out, int out_size)
{
    const float* pred = (const float*)d_in[1];
    const float* tgt  = (const float*)d_in[2];
    float* out = (float*)d_out;

    dim3 g1(128, Bn);
    k_lab<<<g1, 256>>>(pred, tgt);

    dim3 blk(32, 8);
    k_ssim<<<dim3(16, 64, Bn), blk>>>(OFF0, OFF1, 512, 0);
    k_ssim<<<dim3(8, 32, Bn),  blk>>>(OFF1, OFF2, 256, 1);

    k_tail<<<128, 1024>>>(out);
}

// round 8
// speedup vs baseline: 1.5498x; 1.0255x over previous
#include <cuda_runtime.h>
#include <math.h>

#define Bn    8
#define NPIX  (512*512)
#define NBINS 256

#define OFF0 0u
#define OFF1 2097152u
#define OFF2 2621440u
#define OFF3 2752512u
#define OFF4 2785280u

#define G0 0.12007823f
#define G1 0.23388087f
#define G2 0.29208180f
__device__ __constant__ float c_g[5] = {G0, G1, G2, G1, G0};

// interleaved pyramid: d_L[i] = (pred_L, tgt_L)
__device__ float2 d_L[2793472];
__device__ int    d_histd[Bn*3*NBINS];     // signed: pred minus tgt counts
__device__ float  d_l1sum;
__device__ float  d_ssim_sum[Bn*5];
__device__ float  d_cs_sum[Bn*5];
__device__ float  d_l1img[Bn];
__device__ unsigned g_img_done[Bn];
__device__ unsigned g_final;

// ---------------- RGB -> normalized LAB -------------------------------------
__device__ __forceinline__ float srgb_lin(float x)
{
    if (x <= 0.04045f) return x * (1.f/12.92f);
    float y = (fmaxf(x, 1e-4f) + 0.055f) * (1.f/1.055f);
    return __powf(y, 2.4f);
}

__device__ __forceinline__ float f_lab(float t)
{
    const float e3 = 0.008856451679035631f;
    if (t <= e3) return t * (841.f/108.f) + (4.f/29.f);
    return __powf(fmaxf(t, 1e-4f), 1.f/3.f);
}

__device__ __forceinline__ void rgb2lab_norm(float r, float g, float b,
                                             float& L, float& A, float& Bc)
{
    float lr = srgb_lin(r), lg = srgb_lin(g), lb = srgb_lin(b);
    float X = lr*0.412453f + lg*0.357580f + lb*0.180423f;
    float Y = lr*0.212671f + lg*0.715160f + lb*0.072169f;
    float Z = lr*0.019334f + lg*0.119193f + lb*0.950227f;
    X *= (1.f/0.950456f);
    Z *= (1.f/1.088754f);
    float fx = f_lab(X), fy = f_lab(Y), fz = f_lab(Z);
    float Ll = 116.f*fy - 16.f;
    float Aa = 500.f*(fx - fy);
    float Bb = 200.f*(fy - fz);
    L  = fminf(fmaxf(Ll * 0.01f,                 0.f), 1.f);
    A  = fminf(fmaxf((Aa*(1.f/110.f)+1.f)*0.5f,  0.f), 1.f);
    Bc = fminf(fmaxf((Bb*(1.f/110.f)+1.f)*0.5f,  0.f), 1.f);
}

__device__ __forceinline__ int bin_of(float v)
{
    int b = (int)(v * 256.f);
    return b > 255 ? 255 : b;
}

// ---------------- fused LAB + signed histogram + L1 + L store ---------------
// grid (128, 8) x 256 threads; 8 px/thread (2 float4 iters)
__global__ void k_lab(const float* __restrict__ pred, const float* __restrict__ tgt)
{
    __shared__ int   sh[3*NBINS];
    __shared__ float red[8];
    int b   = blockIdx.y;
    int tid = threadIdx.x;

    for (int i = tid; i < 3*NBINS; i += 256) sh[i] = 0;
    __syncthreads();

    const size_t ibase = (size_t)b*3*NPIX;
    float l1acc = 0.f;

#pragma unroll
    for (int it = 0; it < 2; it++) {
        int p = blockIdx.x*2048 + it*1024 + tid*4;
        float4 pr = *(const float4*)(pred + ibase + p);
        float4 pg = *(const float4*)(pred + ibase + NPIX + p);
        float4 pb = *(const float4*)(pred + ibase + 2*NPIX + p);
        float4 tr = *(const float4*)(tgt  + ibase + p);
        float4 tg = *(const float4*)(tgt  + ibase + NPIX + p);
        float4 tb = *(const float4*)(tgt  + ibase + 2*NPIX + p);

        float* prf = &pr.x; float* pgf = &pg.x; float* pbf = &pb.x;
        float* trf = &tr.x; float* tgf = &tg.x; float* tbf = &tb.x;
        float pls[4], tls[4];
#pragma unroll
        for (int j = 0; j < 4; j++) {
            float pl, pa, pbc, tl, ta, tbc;
            rgb2lab_norm(prf[j], pgf[j], pbf[j], pl, pa, pbc);
            rgb2lab_norm(trf[j], tgf[j], tbf[j], tl, ta, tbc);
            pls[j] = pl; tls[j] = tl;
            atomicAdd(&sh[0*NBINS + bin_of(pl)],   1);
            atomicAdd(&sh[1*NBINS + bin_of(pa)],   1);
            atomicAdd(&sh[2*NBINS + bin_of(pbc)],  1);
            atomicAdd(&sh[0*NBINS + bin_of(tl)],  -1);
            atomicAdd(&sh[1*NBINS + bin_of(ta)],  -1);
            atomicAdd(&sh[2*NBINS + bin_of(tbc)], -1);
            l1acc += fabsf(pl-tl) + fabsf(pa-ta) + fabsf(pbc-tbc);
        }
        float4* dst = (float4*)&d_L[(size_t)b*NPIX + p];
        dst[0] = make_float4(pls[0], tls[0], pls[1], tls[1]);
        dst[1] = make_float4(pls[2], tls[2], pls[3], tls[3]);
    }
    __syncthreads();

    for (int i = tid; i < 3*NBINS; i += 256) {
        int hd = sh[i];
        if (hd) atomicAdd(&d_histd[b*3*NBINS + i], hd);
    }

    float v = l1acc;
    for (int o = 16; o; o >>= 1) v += __shfl_down_sync(0xffffffffu, v, o);
    int lane = tid & 31, wid = tid >> 5;
    if (lane == 0) red[wid] = v;
    __syncthreads();
    if (wid == 0) {
        v = (lane < 8) ? red[lane] : 0.f;
        for (int o = 4; o; o >>= 1) v += __shfl_down_sync(0xffffffffu, v, o);
        if (lane == 0) atomicAdd(&d_l1sum, v);
    }
}

// ---------------- 32x32 SSIM tile (256 threads, 4 outputs/thread) -----------
struct Unit {
    float2 t[36][36];
    float2 m12[36][32];
    float2 x12[36][32];
    float  a12[36][32];
};

__device__ __forceinline__ void ssim_tile32(Unit& U, int ut,
                                            unsigned off, unsigned offo,
                                            int Hl, int b, int tix, int tiy,
                                            bool pool, float& accS, float& accC)
{
    const float2* src = d_L + off + (size_t)b*Hl*Hl;
    int ox = tix*32, oy = tiy*32;

    // halo load 36x36 float2 (zero pad)
    for (int i = ut; i < 36*36; i += 256) {
        int r = i/36, c = i%36;
        int gy = oy + r - 2, gx = ox + c - 2;
        float2 v = make_float2(0.f, 0.f);
        if (gy >= 0 && gy < Hl && gx >= 0 && gx < Hl)
            v = src[gy*Hl + gx];
        U.t[r][c] = v;
    }
    __syncthreads();

    // horizontal pass: 36 rows x 32 cols of 5 moments
    for (int i = ut; i < 36*32; i += 256) {
        int r = i >> 5, c = i & 31;
        float m1=0.f, m2=0.f, a11=0.f, a22=0.f, cr=0.f;
#pragma unroll
        for (int k = 0; k < 5; k++) {
            float g = c_g[k];
            float2 a = U.t[r][c+k];
            float ga = g*a.x, gq = g*a.y;
            m1 += ga; m2 += gq;
            a11 += ga*a.x; a22 += gq*a.y; cr += ga*a.y;
        }
        U.m12[r][c] = make_float2(m1, m2);
        U.x12[r][c] = make_float2(a11, a22);
        U.a12[r][c] = cr;
    }
    __syncthreads();

    // vertical pass: thread (tx,ty) -> outputs (x=tx, y=4*ty..4*ty+3)
    int tx = ut & 31, ty = ut >> 5;
    int y0 = ty*4;
    float2 mu[4], xx[4];
    float cr4[4];
#pragma unroll
    for (int j = 0; j < 4; j++) {
        mu[j] = make_float2(0.f, 0.f);
        xx[j] = make_float2(0.f, 0.f);
        cr4[j] = 0.f;
    }
#pragma unroll
    for (int k = 0; k < 8; k++) {
        float2 m = U.m12[y0+k][tx];
        float2 x = U.x12[y0+k][tx];
        float  a = U.a12[y0+k][tx];
#pragma unroll
        for (int j = 0; j < 4; j++) {
            int tap = k - j;
            if (tap >= 0 && tap < 5) {
                float w = c_g[tap];
                mu[j].x += w*m.x; mu[j].y += w*m.y;
                xx[j].x += w*x.x; xx[j].y += w*x.y;
                cr4[j]  += w*a;
            }
        }
    }
    const float C1 = 1e-4f, C2 = 9e-4f;
#pragma unroll
    for (int j = 0; j < 4; j++) {
        float s1  = xx[j].x - mu[j].x*mu[j].x;
        float s2  = xx[j].y - mu[j].y*mu[j].y;
        float s12 = cr4[j]  - mu[j].x*mu[j].y;
        float den  = s1 + s2 + C2;
        float num2 = 2.f*s12 + C2;
        accC += num2 / den;
        accS += ((2.f*mu[j].x*mu[j].y + C1) * num2) /
                ((mu[j].x*mu[j].x + mu[j].y*mu[j].y + C1) * den);
    }

    // fused 2x2 avg-pool: 16x16 pooled px, one per thread
    if (pool) {
        int rp = ut >> 4, cp = ut & 15;
        int Ho = Hl >> 1;
        float2 q0 = U.t[2*rp+2][2*cp+2], q1 = U.t[2*rp+2][2*cp+3];
        float2 q2 = U.t[2*rp+3][2*cp+2], q3 = U.t[2*rp+3][2*cp+3];
        float2 pv = make_float2(0.25f*(q0.x+q1.x+q2.x+q3.x),
                                0.25f*(q0.y+q1.y+q2.y+q3.y));
        d_L[(size_t)offo + (size_t)b*Ho*Ho + (size_t)((oy>>1)+rp)*Ho + (ox>>1)+cp] = pv;
    }
    __syncthreads();   // protect tile buffers before any next round
}

// ---------------- 256-thread pair reduce; result valid in thread 0 ----------
__device__ __forceinline__ void reduce256(float& a, float& c,
                                          float* rS, float* rC, int ut)
{
    int lane = ut & 31, wid = ut >> 5;
    for (int o = 16; o; o >>= 1) {
        a += __shfl_down_sync(0xffffffffu, a, o);
        c += __shfl_down_sync(0xffffffffu, c, o);
    }
    if (lane == 0) { rS[wid] = a; rC[wid] = c; }
    __syncthreads();
    if (wid == 0) {
        a = (lane < 8) ? rS[lane] : 0.f;
        c = (lane < 8) ? rC[lane] : 0.f;
        for (int o = 4; o; o >>= 1) {
            a += __shfl_down_sync(0xffffffffu, a, o);
            c += __shfl_down_sync(0xffffffffu, c, o);
        }
    }
    __syncthreads();
}

// ---------------- standalone SSIM kernel (levels 0, 1) ----------------------
__global__ void __launch_bounds__(256)
k_ssim(unsigned off, unsigned offo, int Hl, int lvl)
{
    __shared__ Unit U;
    __shared__ float rS[8], rC[8];
    int b  = blockIdx.z;
    int ut = threadIdx.x;

    float aS = 0.f, aC = 0.f;
    ssim_tile32(U, ut, off, offo, Hl, b, blockIdx.x, blockIdx.y, true, aS, aC);
    reduce256(aS, aC, rS, rC, ut);
    if (ut == 0) {
        atomicAdd(&d_ssim_sum[b*5 + lvl], aS);
        atomicAdd(&d_cs_sum[b*5 + lvl], aC);
    }
}

// ---------------- tail: L2 (128 blocks) + elected L3/L4/hist + final --------
__global__ void __launch_bounds__(256)
k_tail(float* __restrict__ out)
{
    __shared__ Unit U;
    __shared__ float rS[8], rC[8];
    __shared__ float msarr[8];
    __shared__ unsigned rank_s;

    int ut  = threadIdx.x;
    int img = blockIdx.x >> 4;
    int t   = blockIdx.x & 15;

    // -------- L2: 16 tiles/img (128x128, 4x4 tiles), 1 round ----------------
    {
        float aS = 0.f, aC = 0.f;
        ssim_tile32(U, ut, OFF2, OFF3, 128, img, t & 3, t >> 2, true, aS, aC);
        reduce256(aS, aC, rS, rC, ut);
        if (ut == 0) {
            atomicAdd(&d_ssim_sum[img*5 + 2], aS);
            atomicAdd(&d_cs_sum[img*5 + 2], aC);
        }
    }
    __syncthreads();

    // -------- elect last block of this image (no spin) ----------------------
    if (ut == 0) {
        __threadfence();
        rank_s = atomicAdd(&g_img_done[img], 1u);
    }
    __syncthreads();
    if (rank_s != 15u) return;
    __threadfence();                 // acquire peers' L3 pool writes

    // -------- L3: 4 tiles (64x64), sequential rounds -------------------------
    {
        float aS = 0.f, aC = 0.f;
        for (int q = 0; q < 4; q++)
            ssim_tile32(U, ut, OFF3, OFF4, 64, img, q & 1, q >> 1, true, aS, aC);
        reduce256(aS, aC, rS, rC, ut);
        if (ut == 0) {
            d_ssim_sum[img*5 + 3] = aS;
            d_cs_sum[img*5 + 3]   = aC;
        }
    }
    __syncthreads();                 // own L4 pool writes ordered

    // -------- L4: 1 tile (32x32 = whole level) -------------------------------
    {
        float aS = 0.f, aC = 0.f;
        ssim_tile32(U, ut, OFF4, 0, 32, img, 0, 0, false, aS, aC);
        reduce256(aS, aC, rS, rC, ut);
        if (ut == 0) {
            d_ssim_sum[img*5 + 4] = aS;
            d_cs_sum[img*5 + 4]   = aC;
        }
    }

    // -------- this image's histogram L1 --------------------------------------
    {
        float s = 0.f;
        for (int i = ut; i < 3*NBINS; i += 256)
            s += fabsf((float)d_histd[img*3*NBINS + i]);
        float dummy = 0.f;
        reduce256(s, dummy, rS, rC, ut);
        if (ut == 0) d_l1img[img] = s * (1.f/768.f);
    }
    __syncthreads();

    // -------- global elect among the 8 image-winners --------------------------
    if (ut == 0) {
        __threadfence();
        rank_s = atomicAdd(&g_final, 1u);
    }
    __syncthreads();
    if (rank_s != (unsigned)(Bn - 1)) return;
    __threadfence();                 // acquire other winners' results

    // -------- final assembly ---------------------------------------------------
    if (ut < 8) {
        const float wts[5] = {0.0448f, 0.2856f, 0.3001f, 0.2363f, 0.1333f};
        const float cnt[5] = {262144.f, 65536.f, 16384.f, 4096.f, 1024.f};
        float ms = 1.f;
        for (int l = 0; l < 4; l++) {
            float mcs = d_cs_sum[ut*5 + l] / cnt[l];
            ms *= powf((mcs + 1.f)*0.5f, wts[l]);
        }
        float mss4 = d_ssim_sum[ut*5 + 4] / cnt[4];
        ms *= powf((mss4 + 1.f)*0.5f, wts[4]);
        msarr[ut] = 1.f - ms;
    }
    __syncthreads();

    if (ut == 0) {
        float hist_loss = 0.f;
        for (int i = 0; i < 8; i++)
            hist_loss += exp2f((float)(i - 8)) * (d_l1img[i] + 1.f);
        float scaler = (float)NPIX / 20.f;
        hist_loss = hist_loss / 8.f / scaler;
        float lab_l1 = d_l1sum / (float)(Bn*3*NPIX);
        float sl = 0.f;
        for (int i = 0; i < 8; i++) sl += msarr[i];
        sl *= (1.f/8.f);
        out[0] = lab_l1 + hist_loss;
        out[1] = sl;
    }
    __syncthreads();

    // -------- re-zero all state for next graph replay --------------------------
    for (int i = ut; i < Bn*3*NBINS; i += 256) d_histd[i] = 0;
    if (ut < Bn*5) { d_ssim_sum[ut] = 0.f; d_cs_sum[ut] = 0.f; }
    if (ut < Bn)   g_img_done[ut] = 0u;
    if (ut == 0) { d_l1sum = 0.f; g_final = 0u; __threadfence(); }
}

// ---------------- launch ------------------------------------------------------
extern "C" void kernel_launch(void* const* d_in, const int* in_sizes, int n_in,
                              void* d_out, int out_size)
{
    const float* pred = (const float*)d_in[1];
    const float* tgt  = (const float*)d_in[2];
    float* out = (float*)d_out;

    dim3 g1(128, Bn);
    k_lab<<<g1, 256>>>(pred, tgt);

    k_ssim<<<dim3(16, 16, Bn), 256>>>(OFF0, OFF1, 512, 0);
    k_ssim<<<dim3(8, 8, Bn),   256>>>(OFF1, OFF2, 256, 1);

    k_tail<<<128, 256>>>(out);
}

// round 10
// speedup vs baseline: 1.6576x; 1.0696x over previous
#include <cuda_runtime.h>
#include <math.h>

#define Bn    8
#define NPIX  (512*512)
#define NBINS 256

#define OFF0 0u
#define OFF1 2097152u
#define OFF2 2621440u
#define OFF3 2752512u
#define OFF4 2785280u

#define G0 0.12007823f
#define G1 0.23388087f
#define G2 0.29208180f
__device__ __constant__ float c_g[5] = {G0, G1, G2, G1, G0};

// interleaved pyramid: d_L[i] = (pred_L, tgt_L)
__device__ float2 d_L[2793472];
__device__ int    d_histd[Bn*3*NBINS];     // signed: pred minus tgt counts
__device__ float  d_l1sum;
__device__ float  d_ssim_sum[Bn*5];
__device__ float  d_cs_sum[Bn*5];
__device__ float  d_l1img[Bn];

__device__ __forceinline__ void bar_sync(int id)
{
    asm volatile("bar.sync %0, 256;" :: "r"(id) : "memory");
}

// ---------------- RGB -> normalized LAB -------------------------------------
__device__ __forceinline__ float srgb_lin(float x)
{
    if (x <= 0.04045f) return x * (1.f/12.92f);
    float y = (fmaxf(x, 1e-4f) + 0.055f) * (1.f/1.055f);
    return __powf(y, 2.4f);
}

__device__ __forceinline__ float f_lab(float t)
{
    const float e3 = 0.008856451679035631f;
    if (t <= e3) return t * (841.f/108.f) + (4.f/29.f);
    return __powf(fmaxf(t, 1e-4f), 1.f/3.f);
}

__device__ __forceinline__ void rgb2lab_norm(float r, float g, float b,
                                             float& L, float& A, float& Bc)
{
    float lr = srgb_lin(r), lg = srgb_lin(g), lb = srgb_lin(b);
    float X = lr*0.412453f + lg*0.357580f + lb*0.180423f;
    float Y = lr*0.212671f + lg*0.715160f + lb*0.072169f;
    float Z = lr*0.019334f + lg*0.119193f + lb*0.950227f;
    X *= (1.f/0.950456f);
    Z *= (1.f/1.088754f);
    float fx = f_lab(X), fy = f_lab(Y), fz = f_lab(Z);
    float Ll = 116.f*fy - 16.f;
    float Aa = 500.f*(fx - fy);
    float Bb = 200.f*(fy - fz);
    L  = fminf(fmaxf(Ll * 0.01f,                 0.f), 1.f);
    A  = fminf(fmaxf((Aa*(1.f/110.f)+1.f)*0.5f,  0.f), 1.f);
    Bc = fminf(fmaxf((Bb*(1.f/110.f)+1.f)*0.5f,  0.f), 1.f);
}

__device__ __forceinline__ int bin_of(float v)
{
    int b = (int)(v * 256.f);
    return b > 255 ? 255 : b;
}

// ---------------- fused LAB + signed histogram + L1 + L store ---------------
// grid (128, 8) x 256 threads; 8 px/thread
__global__ void k_lab(const float* __restrict__ pred, const float* __restrict__ tgt)
{
    __shared__ int   sh[3*NBINS];
    __shared__ float red[8];
    int b   = blockIdx.y;
    int tid = threadIdx.x;

    for (int i = tid; i < 3*NBINS; i += 256) sh[i] = 0;
    __syncthreads();

    const size_t ibase = (size_t)b*3*NPIX;
    float l1acc = 0.f;

#pragma unroll
    for (int it = 0; it < 2; it++) {
        int p = blockIdx.x*2048 + it*1024 + tid*4;
        float4 pr = *(const float4*)(pred + ibase + p);
        float4 pg = *(const float4*)(pred + ibase + NPIX + p);
        float4 pb = *(const float4*)(pred + ibase + 2*NPIX + p);
        float4 tr = *(const float4*)(tgt  + ibase + p);
        float4 tg = *(const float4*)(tgt  + ibase + NPIX + p);
        float4 tb = *(const float4*)(tgt  + ibase + 2*NPIX + p);

        float* prf = &pr.x; float* pgf = &pg.x; float* pbf = &pb.x;
        float* trf = &tr.x; float* tgf = &tg.x; float* tbf = &tb.x;
        float pls[4], tls[4];
#pragma unroll
        for (int j = 0; j < 4; j++) {
            float pl, pa, pbc, tl, ta, tbc;
            rgb2lab_norm(prf[j], pgf[j], pbf[j], pl, pa, pbc);
            rgb2lab_norm(trf[j], tgf[j], tbf[j], tl, ta, tbc);
            pls[j] = pl; tls[j] = tl;
            atomicAdd(&sh[0*NBINS + bin_of(pl)],   1);
            atomicAdd(&sh[1*NBINS + bin_of(pa)],   1);
            atomicAdd(&sh[2*NBINS + bin_of(pbc)],  1);
            atomicAdd(&sh[0*NBINS + bin_of(tl)],  -1);
            atomicAdd(&sh[1*NBINS + bin_of(ta)],  -1);
            atomicAdd(&sh[2*NBINS + bin_of(tbc)], -1);
            l1acc += fabsf(pl-tl) + fabsf(pa-ta) + fabsf(pbc-tbc);
        }
        float4* dst = (float4*)&d_L[(size_t)b*NPIX + p];
        dst[0] = make_float4(pls[0], tls[0], pls[1], tls[1]);
        dst[1] = make_float4(pls[2], tls[2], pls[3], tls[3]);
    }
    __syncthreads();

    for (int i = tid; i < 3*NBINS; i += 256) {
        int hd = sh[i];
        if (hd) atomicAdd(&d_histd[b*3*NBINS + i], hd);
    }

    float v = l1acc;
    for (int o = 16; o; o >>= 1) v += __shfl_down_sync(0xffffffffu, v, o);
    int lane = tid & 31, wid = tid >> 5;
    if (lane == 0) red[wid] = v;
    __syncthreads();
    if (wid == 0) {
        v = (lane < 8) ? red[lane] : 0.f;
        for (int o = 4; o; o >>= 1) v += __shfl_down_sync(0xffffffffu, v, o);
        if (lane == 0) atomicAdd(&d_l1sum, v);
    }
}

// ---------------- 32x32 SSIM tile (one 256-thread unit) ---------------------
struct Unit {
    float2 t[36][36];
    float2 m12[36][32];
    float2 x12[36][32];
    float  a12[36][32];
    float  redS[8], redC[8];
};

// syncs with named barrier `bar` (256 threads of the unit only)
__device__ __forceinline__ void ssim_tile32(Unit& U, int ut, int bar,
                                            unsigned off, unsigned offo,
                                            int Hl, int b, int tix, int tiy,
                                            bool pool, float& accS, float& accC)
{
    const float2* src = d_L + off + (size_t)b*Hl*Hl;
    int ox = tix*32, oy = tiy*32;

    for (int i = ut; i < 36*36; i += 256) {
        int r = i/36, c = i%36;
        int gy = oy + r - 2, gx = ox + c - 2;
        float2 v = make_float2(0.f, 0.f);
        if (gy >= 0 && gy < Hl && gx >= 0 && gx < Hl)
            v = src[gy*Hl + gx];
        U.t[r][c] = v;
    }
    bar_sync(bar);

    for (int i = ut; i < 36*32; i += 256) {
        int r = i >> 5, c = i & 31;
        float m1=0.f, m2=0.f, a11=0.f, a22=0.f, cr=0.f;
#pragma unroll
        for (int k = 0; k < 5; k++) {
            float g = c_g[k];
            float2 a = U.t[r][c+k];
            float ga = g*a.x, gq = g*a.y;
            m1 += ga; m2 += gq;
            a11 += ga*a.x; a22 += gq*a.y; cr += ga*a.y;
        }
        U.m12[r][c] = make_float2(m1, m2);
        U.x12[r][c] = make_float2(a11, a22);
        U.a12[r][c] = cr;
    }
    bar_sync(bar);

    int tx = ut & 31, ty = ut >> 5;
    int y0 = ty*4;
    float2 mu[4], xx[4];
    float cr4[4];
#pragma unroll
    for (int j = 0; j < 4; j++) {
        mu[j] = make_float2(0.f, 0.f);
        xx[j] = make_float2(0.f, 0.f);
        cr4[j] = 0.f;
    }
#pragma unroll
    for (int k = 0; k < 8; k++) {
        float2 m = U.m12[y0+k][tx];
        float2 x = U.x12[y0+k][tx];
        float  a = U.a12[y0+k][tx];
#pragma unroll
        for (int j = 0; j < 4; j++) {
            int tap = k - j;
            if (tap >= 0 && tap < 5) {
                float w = c_g[tap];
                mu[j].x += w*m.x; mu[j].y += w*m.y;
                xx[j].x += w*x.x; xx[j].y += w*x.y;
                cr4[j]  += w*a;
            }
        }
    }
    const float C1 = 1e-4f, C2 = 9e-4f;
#pragma unroll
    for (int j = 0; j < 4; j++) {
        float s1  = xx[j].x - mu[j].x*mu[j].x;
        float s2  = xx[j].y - mu[j].y*mu[j].y;
        float s12 = cr4[j]  - mu[j].x*mu[j].y;
        float den  = s1 + s2 + C2;
        float num2 = 2.f*s12 + C2;
        accC += num2 / den;
        accS += ((2.f*mu[j].x*mu[j].y + C1) * num2) /
                ((mu[j].x*mu[j].x + mu[j].y*mu[j].y + C1) * den);
    }

    if (pool) {
        int rp = ut >> 4, cp = ut & 15;
        int Ho = Hl >> 1;
        float2 q0 = U.t[2*rp+2][2*cp+2], q1 = U.t[2*rp+2][2*cp+3];
        float2 q2 = U.t[2*rp+3][2*cp+2], q3 = U.t[2*rp+3][2*cp+3];
        float2 pv = make_float2(0.25f*(q0.x+q1.x+q2.x+q3.x),
                                0.25f*(q0.y+q1.y+q2.y+q3.y));
        d_L[(size_t)offo + (size_t)b*Ho*Ho + (size_t)((oy>>1)+rp)*Ho + (ox>>1)+cp] = pv;
    }
    bar_sync(bar);   // protect tile buffers before any next round
}

// ---------------- unit-level (256 thr) pair reduce; result in ut==0 ---------
__device__ __forceinline__ void reduce_unit(Unit& U, float& a, float& c,
                                            int ut, int bar)
{
    int lane = ut & 31, wid = ut >> 5;
    for (int o = 16; o; o >>= 1) {
        a += __shfl_down_sync(0xffffffffu, a, o);
        c += __shfl_down_sync(0xffffffffu, c, o);
    }
    if (lane == 0) { U.redS[wid] = a; U.redC[wid] = c; }
    bar_sync(bar);
    if (wid == 0) {
        a = (lane < 8) ? U.redS[lane] : 0.f;
        c = (lane < 8) ? U.redC[lane] : 0.f;
        for (int o = 4; o; o >>= 1) {
            a += __shfl_down_sync(0xffffffffu, a, o);
            c += __shfl_down_sync(0xffffffffu, c, o);
        }
    }
    bar_sync(bar);
}

// ---------------- batched SSIM level kernel (L0, L1, L2) --------------------
__global__ void __launch_bounds__(256)
k_ssim(unsigned off, unsigned offo, int Hl, int lvl)
{
    __shared__ Unit U;
    int b  = blockIdx.z;
    int ut = threadIdx.x;

    float aS = 0.f, aC = 0.f;
    ssim_tile32(U, ut, 1, off, offo, Hl, b, blockIdx.x, blockIdx.y, true, aS, aC);
    reduce_unit(U, aS, aC, ut, 1);
    if (ut == 0) {
        atomicAdd(&d_ssim_sum[b*5 + lvl], aS);
        atomicAdd(&d_cs_sum[b*5 + lvl], aC);
    }
}

// ---------------- tail: L3 (4 units, 1 round) + L4 + hist; 8 blocks ---------
__global__ void __launch_bounds__(1024, 1)
k_tail8()
{
    extern __shared__ Unit Us[];      // 4 units
    __shared__ float hred[32];

    int tid  = threadIdx.x;
    int ublk = tid >> 8;
    int ut   = tid & 255;
    int b    = blockIdx.x;
    Unit& U  = Us[ublk];
    int bar  = 1 + ublk;              // bar 0 reserved for __syncthreads

    // -------- L3: 4 tiles (64x64), one per unit, single round ---------------
    {
        float aS = 0.f, aC = 0.f;
        ssim_tile32(U, ut, bar, OFF3, OFF4, 64, b, ublk & 1, ublk >> 1, true, aS, aC);
        reduce_unit(U, aS, aC, ut, bar);
        if (ut == 0) {
            atomicAdd(&d_ssim_sum[b*5 + 3], aS);
            atomicAdd(&d_cs_sum[b*5 + 3], aC);
        }
    }
    __syncthreads();                  // all units' L4 pool writes visible

    // -------- L4: 1 tile (whole 32x32 level), unit 0 only --------------------
    if (ublk == 0) {
        float aS = 0.f, aC = 0.f;
        ssim_tile32(U, ut, bar, OFF4, 0, 32, b, 0, 0, false, aS, aC);
        reduce_unit(U, aS, aC, ut, bar);
        if (ut == 0) {
            d_ssim_sum[b*5 + 4] = aS;
            d_cs_sum[b*5 + 4]   = aC;
        }
    }

    // -------- histogram L1 for this image (all 1024 threads) -----------------
    {
        float s = (tid < 3*NBINS) ? fabsf((float)d_histd[b*3*NBINS + tid]) : 0.f;
        int lane = tid & 31, wid = tid >> 5;
        for (int o = 16; o; o >>= 1) s += __shfl_down_sync(0xffffffffu, s, o);
        if (lane == 0) hred[wid] = s;
        __syncthreads();
        if (wid == 0) {
            s = hred[lane];
            for (int o = 16; o; o >>= 1) s += __shfl_down_sync(0xffffffffu, s, o);
            if (lane == 0) d_l1img[b] = s * (1.f/768.f);
        }
    }
}

// ---------------- final assembly + state re-zero (1 block) ------------------
__global__ void __launch_bounds__(256)
k_final(float* __restrict__ out)
{
    __shared__ float msarr[8];
    int ut = threadIdx.x;

    if (ut < 8) {
        const float wts[5] = {0.0448f, 0.2856f, 0.3001f, 0.2363f, 0.1333f};
        const float cnt[5] = {262144.f, 65536.f, 16384.f, 4096.f, 1024.f};
        float ms = 1.f;
        for (int l = 0; l < 4; l++) {
            float mcs = d_cs_sum[ut*5 + l] / cnt[l];
            ms *= powf((mcs + 1.f)*0.5f, wts[l]);
        }
        float mss4 = d_ssim_sum[ut*5 + 4] / cnt[4];
        ms *= powf((mss4 + 1.f)*0.5f, wts[4]);
        msarr[ut] = 1.f - ms;
    }
    __syncthreads();

    if (ut == 0) {
        float hist_loss = 0.f;
        for (int i = 0; i < 8; i++)
            hist_loss += exp2f((float)(i - 8)) * (d_l1img[i] + 1.f);
        float scaler = (float)NPIX / 20.f;
        hist_loss = hist_loss / 8.f / scaler;
        float lab_l1 = d_l1sum / (float)(Bn*3*NPIX);
        float sl = 0.f;
        for (int i = 0; i < 8; i++) sl += msarr[i];
        sl *= (1.f/8.f);
        out[0] = lab_l1 + hist_loss;
        out[1] = sl;
    }

    // re-zero accumulators for next graph replay
    for (int i = ut; i < Bn*3*NBINS; i += 256) d_histd[i] = 0;
    if (ut < Bn*5) { d_ssim_sum[ut] = 0.f; d_cs_sum[ut] = 0.f; }
    if (ut == 0) d_l1sum = 0.f;
}

// ---------------- launch ------------------------------------------------------
extern "C" void kernel_launch(void* const* d_in, const int* in_sizes, int n_in,
                              void* d_out, int out_size)
{
    const float* pred = (const float*)d_in[1];
    const float* tgt  = (const float*)d_in[2];
    float* out = (float*)d_out;

    static int smem_set = 0;
    int tail_smem = (int)(4*sizeof(Unit));
    if (!smem_set) {
        cudaFuncSetAttribute(k_tail8, cudaFuncAttributeMaxDynamicSharedMemorySize,
                             tail_smem);
        smem_set = 1;
    }

    dim3 g1(128, Bn);
    k_lab<<<g1, 256>>>(pred, tgt);

    k_ssim<<<dim3(16, 16, Bn), 256>>>(OFF0, OFF1, 512, 0);
    k_ssim<<<dim3(8, 8, Bn),   256>>>(OFF1, OFF2, 256, 1);
    k_ssim<<<dim3(4, 4, Bn),   256>>>(OFF2, OFF3, 128, 2);

    k_tail8<<<Bn, 1024, tail_smem>>>();
    k_final<<<1, 256>>>(out);
}